// round 3
// baseline (speedup 1.0000x reference)
#include <cuda_runtime.h>
#include <math.h>
#include <stdint.h>

#define NAC 20000
#define NBC 20000
#define NNC 40000
#define EC  150000

// ---------------------------------------------------------------------------
// Scratch (static device globals)
// ---------------------------------------------------------------------------
__device__ float g_h[NNC * 128];             // node features [a;b]
__device__ float g_feat_a[NAC * 640];        // q|kt0|vt0|kt1|vt1 for type a
__device__ float g_feat_b[NBC * 384];        // q|kt2|vt2 for type b
__device__ float g_wcat[3 * 128 * 1024];     // folded weights per layer
__device__ float g_bcat[3 * 1024];           // folded biases
__device__ float g_alpha[3 * EC * 4];        // CSR-ordered logits
__device__ float g_agg[NNC * 128];
__device__ float g_gout[NNC * 128];
__device__ int   g_deg[NNC + 1];
__device__ int   g_rowptr[NNC + 1];
__device__ int   g_cursor[NNC];
__device__ int   g_bsum[64];
__device__ int   g_cse[3 * EC];              // src | et<<29
__device__ float g_x1[NNC];
__device__ float g_score[NNC];
__device__ float g_stmp[NNC];

__device__ __forceinline__ float gelu_f(float x) {
    return 0.5f * x * (1.0f + erff(x * 0.7071067811865475f));
}

// Packed f32x2 helpers (Blackwell FFMA2 — PTX-only, ptxas won't auto-fuse)
__device__ __forceinline__ unsigned long long bcast2(float x) {
    unsigned long long r;
    unsigned u = __float_as_uint(x);
    asm("mov.b64 %0, {%1, %1};" : "=l"(r) : "r"(u));
    return r;
}
__device__ __forceinline__ void fma2(unsigned long long& d, unsigned long long a,
                                     unsigned long long b) {
    asm("fma.rn.f32x2 %0, %1, %2, %0;" : "+l"(d) : "l"(a), "l"(b));
}
__device__ __forceinline__ void unpk2(unsigned long long v, float& lo, float& hi) {
    unsigned a, b;
    asm("mov.b64 {%0, %1}, %2;" : "=r"(a), "=r"(b) : "l"(v));
    lo = __uint_as_float(a); hi = __uint_as_float(b);
}

// ---------------------------------------------------------------------------
__global__ void k_copy_in(const float* __restrict__ xa, const float* __restrict__ xb,
                          float* __restrict__ h, int na128, int nb128) {
    int i = blockIdx.x * blockDim.x + threadIdx.x;
    if (i < na128) h[i] = xa[i];
    if (i < nb128) h[na128 + i] = xb[i];
}

// ---------------------------------------------------------------------------
// Fold relation transforms into GEMM weights.
// ---------------------------------------------------------------------------
__global__ void k_fold(const float* __restrict__ Wkqv, const float* __restrict__ bkqv,
                       const float* __restrict__ arel, const float* __restrict__ mrel,
                       float* __restrict__ wcat, float* __restrict__ bcat) {
    int idx = blockIdx.x * blockDim.x + threadIdx.x;
    const int TOT = 3 * 129 * 1024;
    if (idx >= TOT) return;
    int L = idx / (129 * 1024);
    int r = idx % (129 * 1024);
    int i = r / 1024;            // 0..128 (128 = bias row)
    int c = r % 1024;
    int type = (c >= 640) ? 1 : 0;
    int cc = c - (type ? 640 : 0);
    int part = cc >> 7, wi = cc & 127;
    const float* Wrow;
    if (i < 128) Wrow = Wkqv + ((size_t)(L * 2 + type) * 128 + i) * 384;
    else         Wrow = bkqv + (size_t)(L * 2 + type) * 384;
    float val;
    if (part == 0) {
        val = Wrow[128 + wi];                       // q part
    } else {
        int et, kv;
        if (type == 0) { et = (part - 1) >> 1; kv = (part - 1) & 1; }
        else           { et = 2;               kv = part - 1; }
        int h = wi >> 5, e = wi & 31;
        const float* rel = (kv ? mrel : arel) + ((size_t)(L * 3 + et) * 4 + h) * 1024 + e;
        const float* wsrc = Wrow + (kv ? 256 : 0) + h * 32;
        float s = 0.f;
#pragma unroll
        for (int d = 0; d < 32; d++) s += wsrc[d] * rel[d * 32];
        val = s;
    }
    if (i < 128) wcat[(size_t)L * 131072 + (size_t)i * 1024 + c] = val;
    else         bcat[L * 1024 + c] = val;
}

// ---------------------------------------------------------------------------
// FFMA2 SGEMM: C[M,N] = act(A)[M,128] @ B[128,N] + bias.
// 128x128 tile, BK=16, 256 threads, 8x8 microtile with f32x2 packed FMA.
// N must be a multiple of 128. K fixed = 128.
// ---------------------------------------------------------------------------
template <bool GELU_A>
__global__ void __launch_bounds__(256)
k_gemm_f2(const float* __restrict__ A, int lda,
          const float* __restrict__ B, int ldb,
          const float* __restrict__ bias,
          float* __restrict__ C, int ldc, int M) {
    __shared__ __align__(16) float As[16][128];
    __shared__ __align__(16) float Bs[16][128];
    int tid = threadIdx.x;
    int row0 = blockIdx.y * 128, col0 = blockIdx.x * 128;
    int tx = tid & 15;       // N dir: 8 cols
    int ty = tid >> 4;       // M dir: 8 rows
    unsigned long long acc[4][8];
#pragma unroll
    for (int i = 0; i < 4; i++)
#pragma unroll
        for (int j = 0; j < 8; j++) acc[i][j] = 0ULL;

    int arow = tid >> 1;            // 0..127
    int ak   = (tid & 1) << 3;      // 0 or 8
    int brow = tid >> 4;            // 0..15
    int bcol = (tid & 15) << 3;     // 0..120
    const float* Aptr = A + (size_t)(row0 + arow) * lda + ak;
    bool aval = (row0 + arow) < M;
    const float* Bptr = B + (size_t)brow * ldb + col0 + bcol;

    for (int k0 = 0; k0 < 128; k0 += 16) {
        float4 a0 = make_float4(0.f, 0.f, 0.f, 0.f);
        float4 a1 = make_float4(0.f, 0.f, 0.f, 0.f);
        if (aval) {
            a0 = *(const float4*)(Aptr + k0);
            a1 = *(const float4*)(Aptr + k0 + 4);
        }
        if (GELU_A) {
            a0.x = gelu_f(a0.x); a0.y = gelu_f(a0.y); a0.z = gelu_f(a0.z); a0.w = gelu_f(a0.w);
            a1.x = gelu_f(a1.x); a1.y = gelu_f(a1.y); a1.z = gelu_f(a1.z); a1.w = gelu_f(a1.w);
        }
        As[ak + 0][arow] = a0.x; As[ak + 1][arow] = a0.y;
        As[ak + 2][arow] = a0.z; As[ak + 3][arow] = a0.w;
        As[ak + 4][arow] = a1.x; As[ak + 5][arow] = a1.y;
        As[ak + 6][arow] = a1.z; As[ak + 7][arow] = a1.w;
        *(float4*)&Bs[brow][bcol]     = *(const float4*)(Bptr + (size_t)k0 * ldb);
        *(float4*)&Bs[brow][bcol + 4] = *(const float4*)(Bptr + (size_t)k0 * ldb + 4);
        __syncthreads();
#pragma unroll
        for (int kk = 0; kk < 16; kk++) {
            const ulonglong2* ap2 = reinterpret_cast<const ulonglong2*>(&As[kk][ty * 8]);
            ulonglong2 p0 = ap2[0], p1 = ap2[1];
            float4 bv0 = *(const float4*)&Bs[kk][tx * 8];
            float4 bv1 = *(const float4*)&Bs[kk][tx * 8 + 4];
            unsigned long long bb[8];
            bb[0] = bcast2(bv0.x); bb[1] = bcast2(bv0.y);
            bb[2] = bcast2(bv0.z); bb[3] = bcast2(bv0.w);
            bb[4] = bcast2(bv1.x); bb[5] = bcast2(bv1.y);
            bb[6] = bcast2(bv1.z); bb[7] = bcast2(bv1.w);
#pragma unroll
            for (int j = 0; j < 8; j++) {
                fma2(acc[0][j], p0.x, bb[j]);
                fma2(acc[1][j], p0.y, bb[j]);
                fma2(acc[2][j], p1.x, bb[j]);
                fma2(acc[3][j], p1.y, bb[j]);
            }
        }
        __syncthreads();
    }

    float4 bb0 = *(const float4*)(bias + col0 + tx * 8);
    float4 bb1 = *(const float4*)(bias + col0 + tx * 8 + 4);
    float bsc[8] = {bb0.x, bb0.y, bb0.z, bb0.w, bb1.x, bb1.y, bb1.z, bb1.w};
#pragma unroll
    for (int ap = 0; ap < 4; ap++) {
        int r_lo = row0 + ty * 8 + ap * 2;
        float lo[8], hi[8];
#pragma unroll
        for (int j = 0; j < 8; j++) {
            unpk2(acc[ap][j], lo[j], hi[j]);
            lo[j] += bsc[j]; hi[j] += bsc[j];
        }
        if (r_lo < M) {
            float* p = C + (size_t)r_lo * ldc + col0 + tx * 8;
            *(float4*)p       = make_float4(lo[0], lo[1], lo[2], lo[3]);
            *(float4*)(p + 4) = make_float4(lo[4], lo[5], lo[6], lo[7]);
        }
        if (r_lo + 1 < M) {
            float* p = C + (size_t)(r_lo + 1) * ldc + col0 + tx * 8;
            *(float4*)p       = make_float4(hi[0], hi[1], hi[2], hi[3]);
            *(float4*)(p + 4) = make_float4(hi[4], hi[5], hi[6], hi[7]);
        }
    }
}

// ---------------------------------------------------------------------------
// CSR build
// ---------------------------------------------------------------------------
__global__ void k_zero_deg(int* d, int n) {
    int i = blockIdx.x * blockDim.x + threadIdx.x;
    if (i < n) d[i] = 0;
}
__global__ void k_count(const int* __restrict__ aa, const int* __restrict__ ab,
                        const int* __restrict__ ba, int* __restrict__ deg, int E, int Na) {
    int i = blockIdx.x * blockDim.x + threadIdx.x;
    if (i >= 3 * E) return;
    int dst;
    if (i < E) dst = aa[E + i];
    else if (i < 2 * E) dst = ab[E + (i - E)] + Na;
    else dst = ba[E + (i - 2 * E)];
    atomicAdd(&deg[dst + 1], 1);
}
// Multi-block scan: pass 1 — per-block inclusive scan + block sums
__global__ void k_scan1(const int* __restrict__ deg, int* __restrict__ rowptr,
                        int* __restrict__ bsum, int n) {
    __shared__ int buf[1024];
    int i = blockIdx.x * 1024 + threadIdx.x;
    int v = (i < n) ? deg[i] : 0;
    buf[threadIdx.x] = v;
    __syncthreads();
    for (int o = 1; o < 1024; o <<= 1) {
        int u = (threadIdx.x >= o) ? buf[threadIdx.x - o] : 0;
        __syncthreads();
        buf[threadIdx.x] += u;
        __syncthreads();
    }
    if (i < n) rowptr[i] = buf[threadIdx.x];
    if (threadIdx.x == 1023) bsum[blockIdx.x] = buf[1023];
}
// pass 2 — exclusive scan of block sums (nb <= 64)
__global__ void k_scan2(int* __restrict__ bsum, int nb) {
    __shared__ int s[64];
    int t = threadIdx.x;
    int v = (t < nb) ? bsum[t] : 0;
    s[t] = v;
    __syncthreads();
    for (int o = 1; o < 64; o <<= 1) {
        int u = (t >= o) ? s[t - o] : 0;
        __syncthreads();
        s[t] += u;
        __syncthreads();
    }
    if (t < nb) bsum[t] = s[t] - v;   // exclusive
}
// pass 3 — add block offsets, init cursor
__global__ void k_scan3(const int* __restrict__ bsum, int* __restrict__ rowptr,
                        int* __restrict__ cursor, int n, int N) {
    int i = blockIdx.x * blockDim.x + threadIdx.x;
    if (i >= n) return;
    int v = rowptr[i] + bsum[i >> 10];
    rowptr[i] = v;
    if (i < N) cursor[i] = v;
}
__global__ void k_fill(const int* __restrict__ aa, const int* __restrict__ ab,
                       const int* __restrict__ ba, int* __restrict__ cursor,
                       int* __restrict__ cse, int E, int Na) {
    int i = blockIdx.x * blockDim.x + threadIdx.x;
    if (i >= 3 * E) return;
    int src, dst, et;
    if (i < E)            { et = 0; src = aa[i]; dst = aa[E + i]; }
    else if (i < 2 * E)   { et = 1; int j = i - E;     src = ab[j]; dst = ab[E + j] + Na; }
    else                  { et = 2; int j = i - 2 * E; src = ba[j]; dst = ba[E + j]; }
    int pos = atomicAdd(&cursor[dst], 1);
    cse[pos] = src | (et << 29);
}

// ---------------------------------------------------------------------------
// Fused HGT edge softmax-aggregate. One warp per dst node.
// ---------------------------------------------------------------------------
__global__ void k_hgt_edges(const float* __restrict__ fa, const float* __restrict__ fb,
                            const int* __restrict__ rowptr, const int* __restrict__ cse,
                            const float* __restrict__ prelL,
                            float* __restrict__ alpha, float* __restrict__ agg,
                            int Na, int N) {
    __shared__ float sp[12];
    if (threadIdx.x < 12) sp[threadIdx.x] = prelL[threadIdx.x];
    __syncthreads();
    int warp = (blockIdx.x * blockDim.x + threadIdx.x) >> 5;
    int lane = threadIdx.x & 31;
    if (warp >= N) return;
    int n = warp;
    const float* qrow = (n < Na) ? (fa + (size_t)n * 640) : (fb + (size_t)(n - Na) * 384);
    float4 q4 = *(const float4*)(qrow + lane * 4);
    int h = lane >> 3;
    int beg = rowptr[n], end = rowptr[n + 1];
    float mx = -INFINITY;
    for (int idx = beg; idx < end; idx++) {
        int p = cse[idx];
        int et = p >> 29, src = p & 0x1FFFFFFF;
        const float* kb = (et < 2) ? (fa + (size_t)src * 640 + 128 + (et << 8))
                                   : (fb + (size_t)src * 384 + 128);
        float4 k4 = *(const float4*)(kb + lane * 4);
        float s = q4.x * k4.x + q4.y * k4.y + q4.z * k4.z + q4.w * k4.w;
        s += __shfl_xor_sync(0xffffffffu, s, 1);
        s += __shfl_xor_sync(0xffffffffu, s, 2);
        s += __shfl_xor_sync(0xffffffffu, s, 4);
        float lg = s * sp[et * 4 + h] * 0.17677669529663687f;
        if ((lane & 7) == 0) alpha[(size_t)idx * 4 + h] = lg;
        mx = fmaxf(mx, lg);
    }
    float sum = 0.f;
    float4 acc = make_float4(0.f, 0.f, 0.f, 0.f);
    for (int idx = beg; idx < end; idx++) {
        int p = cse[idx];
        int et = p >> 29, src = p & 0x1FFFFFFF;
        const float* vb = (et < 2) ? (fa + (size_t)src * 640 + 256 + (et << 8))
                                   : (fb + (size_t)src * 384 + 256);
        float lg = alpha[(size_t)idx * 4 + h];
        float w = expf(lg - mx);
        sum += w;
        float4 v4 = *(const float4*)(vb + lane * 4);
        acc.x += w * v4.x; acc.y += w * v4.y; acc.z += w * v4.z; acc.w += w * v4.w;
    }
    float inv = 1.f / (sum + 1e-16f);
    acc.x *= inv; acc.y *= inv; acc.z *= inv; acc.w *= inv;
    *(float4*)(agg + (size_t)n * 128 + lane * 4) = acc;
}

// ---------------------------------------------------------------------------
// Epilogue: h = gelu( [LN]( s*g + (1-s)*h ) )
// ---------------------------------------------------------------------------
__global__ void k_epilogue(const float* __restrict__ g, float* __restrict__ h,
                           const float* __restrict__ skipv,
                           const float* __restrict__ lng, const float* __restrict__ lnb,
                           int doLN) {
    int n = blockIdx.x, t = threadIdx.x;
    float s = 1.0f / (1.0f + expf(-skipv[0]));
    size_t idx = (size_t)n * 128 + t;
    float v = s * g[idx] + (1.0f - s) * h[idx];
    if (doLN) {
        float sv = v, sq = v * v;
#pragma unroll
        for (int o = 16; o > 0; o >>= 1) {
            sv += __shfl_down_sync(0xffffffffu, sv, o);
            sq += __shfl_down_sync(0xffffffffu, sq, o);
        }
        __shared__ float s1[4], s2[4];
        int w = t >> 5;
        if ((t & 31) == 0) { s1[w] = sv; s2[w] = sq; }
        __syncthreads();
        float mu = (s1[0] + s1[1] + s1[2] + s1[3]) * 0.0078125f;
        float eq = (s2[0] + s2[1] + s2[2] + s2[3]) * 0.0078125f;
        float var = eq - mu * mu;
        v = (v - mu) * rsqrtf(var + 1e-5f) * lng[t] + lnb[t];
    }
    h[idx] = gelu_f(v);
}

// ---------------------------------------------------------------------------
// GAT scorer via CSR (+analytic self loops)
// ---------------------------------------------------------------------------
__global__ void k_x1(const float* __restrict__ h, const float* __restrict__ Wg,
                     float* __restrict__ x1, int N) {
    int gw = (blockIdx.x * blockDim.x + threadIdx.x) >> 5;
    int lane = threadIdx.x & 31;
    if (gw >= N) return;
    const float* row = h + (size_t)gw * 128;
    float v = row[lane] * Wg[lane] + row[32 + lane] * Wg[32 + lane]
            + row[64 + lane] * Wg[64 + lane] + row[96 + lane] * Wg[96 + lane];
    v += __shfl_down_sync(0xffffffffu, v, 16);
    v += __shfl_down_sync(0xffffffffu, v, 8);
    v += __shfl_down_sync(0xffffffffu, v, 4);
    v += __shfl_down_sync(0xffffffffu, v, 2);
    v += __shfl_down_sync(0xffffffffu, v, 1);
    if (lane == 0) x1[gw] = v;
}

__global__ void k_gat(const float* __restrict__ x1, const int* __restrict__ rowptr,
                      const int* __restrict__ cse, const float* __restrict__ as_,
                      const float* __restrict__ ad_, const float* __restrict__ bg,
                      float* __restrict__ score, int Na, int N) {
    int n = blockIdx.x * blockDim.x + threadIdx.x;
    if (n >= N) return;
    float a_s = as_[0], a_d = ad_[0];
    float xd = x1[n];
    float eself = xd * (a_s + a_d);
    eself = eself > 0.f ? eself : 0.2f * eself;
    float m = eself;
    int beg = rowptr[n], end = rowptr[n + 1];
    for (int i = beg; i < end; i++) {
        int p = cse[i];
        int src = (p & 0x1FFFFFFF) + (((p >> 29) == 2) ? Na : 0);
        float e = x1[src] * a_s + xd * a_d;
        e = e > 0.f ? e : 0.2f * e;
        m = fmaxf(m, e);
    }
    float w = expf(eself - m), s = w, num = w * xd;
    for (int i = beg; i < end; i++) {
        int p = cse[i];
        int src = (p & 0x1FFFFFFF) + (((p >> 29) == 2) ? Na : 0);
        float e = x1[src] * a_s + xd * a_d;
        e = e > 0.f ? e : 0.2f * e;
        float ww = expf(e - m);
        s += ww; num += ww * x1[src];
    }
    score[n] = num / (s + 1e-16f) + bg[0];
}

// ---------------------------------------------------------------------------
// Final: top-K=8, gated readout, 3-layer MLP, nan_to_num.
// ---------------------------------------------------------------------------
__global__ void k_final(const float* __restrict__ h, const float* __restrict__ score,
                        float* __restrict__ stmp,
                        const float* __restrict__ W1, const float* __restrict__ b1,
                        const float* __restrict__ W2, const float* __restrict__ b2,
                        const float* __restrict__ W3, const float* __restrict__ b3,
                        float* __restrict__ out, int N) {
    const float NEG_INF = __int_as_float(0xff800000);
    __shared__ float sred[256];
    __shared__ int   sidx[256];
    __shared__ float hp[1024];
    __shared__ int   perm[8];
    __shared__ float vals[8];
    __shared__ float v1[128];
    __shared__ float v2[64];
    int t = threadIdx.x;

    for (int i = t; i < N; i += 256) stmp[i] = score[i];
    __syncthreads();

    for (int k = 0; k < 8; k++) {
        float bv = NEG_INF; int bi = 0x7fffffff;
        for (int i = t; i < N; i += 256) {
            float v = stmp[i];
            if (v > bv || (v == bv && i < bi)) { bv = v; bi = i; }
        }
        sred[t] = bv; sidx[t] = bi;
        __syncthreads();
        for (int s = 128; s > 0; s >>= 1) {
            if (t < s) {
                if (sred[t + s] > sred[t] ||
                    (sred[t + s] == sred[t] && sidx[t + s] < sidx[t])) {
                    sred[t] = sred[t + s]; sidx[t] = sidx[t + s];
                }
            }
            __syncthreads();
        }
        if (t == 0) { perm[k] = sidx[0]; vals[k] = sred[0]; stmp[sidx[0]] = NEG_INF; }
        __syncthreads();
    }

    for (int i = t; i < 1024; i += 256) {
        int k = i >> 7, j = i & 127;
        hp[i] = h[(size_t)perm[k] * 128 + j] * tanhf(vals[k]);
    }
    __syncthreads();

    if (t < 128) {
        float acc = b1[t];
        for (int i = 0; i < 1024; i++) acc += hp[i] * W1[i * 128 + t];
        v1[t] = gelu_f(acc);
    }
    __syncthreads();
    if (t < 64) {
        float acc = b2[t];
        for (int i = 0; i < 128; i++) acc += v1[i] * W2[i * 64 + t];
        v2[t] = gelu_f(acc);
    }
    __syncthreads();
    if (t < 16) {
        float acc = b3[t];
        for (int i = 0; i < 64; i++) acc += v2[i] * W3[i * 16 + t];
        float r = gelu_f(acc);
        if (isnan(r)) r = 0.f;
        else if (isinf(r)) r = (r > 0.f) ? 3.4028234663852886e38f : -3.4028234663852886e38f;
        out[t] = r;
    }
}

// ---------------------------------------------------------------------------
static inline int cdiv(int a, int b) { return (a + b - 1) / b; }

extern "C" void kernel_launch(void* const* d_in, const int* in_sizes, int n_in,
                              void* d_out, int out_size) {
    const float* x_a   = (const float*)d_in[0];
    const float* x_b   = (const float*)d_in[1];
    const int*   ei_aa = (const int*)d_in[2];
    const int*   ei_ab = (const int*)d_in[3];
    const int*   ei_ba = (const int*)d_in[4];
    const float* Wkqv  = (const float*)d_in[5];
    const float* bkqv  = (const float*)d_in[6];
    const float* Wout  = (const float*)d_in[7];
    const float* bout  = (const float*)d_in[8];
    const float* skip  = (const float*)d_in[9];
    const float* arel  = (const float*)d_in[10];
    const float* mrel  = (const float*)d_in[11];
    const float* prel  = (const float*)d_in[12];
    const float* ln_g  = (const float*)d_in[13];
    const float* ln_b  = (const float*)d_in[14];
    const float* Wgat  = (const float*)d_in[15];
    const float* att_s = (const float*)d_in[16];
    const float* att_d = (const float*)d_in[17];
    const float* bgat  = (const float*)d_in[18];
    const float* W1    = (const float*)d_in[19];
    const float* b1    = (const float*)d_in[20];
    const float* W2    = (const float*)d_in[21];
    const float* b2    = (const float*)d_in[22];
    const float* W3    = (const float*)d_in[23];
    const float* b3    = (const float*)d_in[24];

    int Na = in_sizes[0] / 128;
    int Nb = in_sizes[1] / 128;
    int N  = Na + Nb;
    int E  = in_sizes[2] / 2;

    float *hbuf, *fa, *fb, *wcat, *bcat, *alphab, *aggb, *goutb, *x1b, *scoreb, *stmpb;
    int *degb, *rowptrb, *cursorb, *cseb, *bsumb;
    cudaGetSymbolAddress((void**)&hbuf, g_h);
    cudaGetSymbolAddress((void**)&fa, g_feat_a);
    cudaGetSymbolAddress((void**)&fb, g_feat_b);
    cudaGetSymbolAddress((void**)&wcat, g_wcat);
    cudaGetSymbolAddress((void**)&bcat, g_bcat);
    cudaGetSymbolAddress((void**)&alphab, g_alpha);
    cudaGetSymbolAddress((void**)&aggb, g_agg);
    cudaGetSymbolAddress((void**)&goutb, g_gout);
    cudaGetSymbolAddress((void**)&degb, g_deg);
    cudaGetSymbolAddress((void**)&rowptrb, g_rowptr);
    cudaGetSymbolAddress((void**)&cursorb, g_cursor);
    cudaGetSymbolAddress((void**)&cseb, g_cse);
    cudaGetSymbolAddress((void**)&bsumb, g_bsum);
    cudaGetSymbolAddress((void**)&x1b, g_x1);
    cudaGetSymbolAddress((void**)&scoreb, g_score);
    cudaGetSymbolAddress((void**)&stmpb, g_stmp);

    // inputs + CSR build + weight folding (reused across layers)
    {
        int tot = (Na > Nb ? Na : Nb) * 128;
        k_copy_in<<<cdiv(tot, 256), 256>>>(x_a, x_b, hbuf, Na * 128, Nb * 128);
    }
    int n1 = N + 1;
    int nb = cdiv(n1, 1024);
    k_zero_deg<<<cdiv(n1, 256), 256>>>(degb, n1);
    k_count<<<cdiv(3 * E, 256), 256>>>(ei_aa, ei_ab, ei_ba, degb, E, Na);
    k_scan1<<<nb, 1024>>>(degb, rowptrb, bsumb, n1);
    k_scan2<<<1, 64>>>(bsumb, nb);
    k_scan3<<<cdiv(n1, 256), 256>>>(bsumb, rowptrb, cursorb, n1, N);
    k_fill<<<cdiv(3 * E, 256), 256>>>(ei_aa, ei_ab, ei_ba, cursorb, cseb, E, Na);
    k_fold<<<cdiv(3 * 129 * 1024, 256), 256>>>(Wkqv, bkqv, arel, mrel, wcat, bcat);

    int mbA = cdiv(Na, 128), mbB = cdiv(Nb, 128);

    for (int L = 0; L < 3; L++) {
        // feature GEMMs (q + folded kt/vt)
        k_gemm_f2<false><<<dim3(5, mbA), 256>>>(hbuf, 128,
            wcat + (size_t)L * 131072, 1024, bcat + L * 1024, fa, 640, Na);
        k_gemm_f2<false><<<dim3(3, mbB), 256>>>(hbuf + (size_t)Na * 128, 128,
            wcat + (size_t)L * 131072 + 640, 1024, bcat + L * 1024 + 640, fb, 384, Nb);
        // fused edge softmax-aggregate
        k_hgt_edges<<<cdiv(N * 32, 256), 256>>>(fa, fb, rowptrb, cseb,
            prel + L * 12, alphab, aggb, Na, N);
        // out GEMM with fused gelu-on-input
        for (int t = 0; t < 2; t++) {
            int Nt = t ? Nb : Na;
            size_t off = (size_t)(t ? Na : 0) * 128;
            k_gemm_f2<true><<<dim3(1, cdiv(Nt, 128)), 256>>>(aggb + off, 128,
                Wout + (size_t)(L * 2 + t) * 16384, 128,
                bout + (size_t)(L * 2 + t) * 128, goutb + off, 128, Nt);
        }
        for (int t = 0; t < 2; t++) {
            int Nt = t ? Nb : Na;
            size_t off = (size_t)(t ? Na : 0) * 128;
            k_epilogue<<<Nt, 128>>>(goutb + off, hbuf + off, skip + (L * 2 + t),
                                    ln_g + t * 128, ln_b + t * 128, (L == 0) ? 1 : 0);
        }
    }

    // GAT scorer + SAGPool + MLP
    k_x1<<<cdiv(N * 32, 256), 256>>>(hbuf, Wgat, x1b, N);
    k_gat<<<cdiv(N, 256), 256>>>(x1b, rowptrb, cseb, att_s, att_d, bgat, scoreb, Na, N);
    k_final<<<1, 256>>>(hbuf, scoreb, stmpb, W1, b1, W2, b2, W3, b3, (float*)d_out, N);
}

// round 5
// speedup vs baseline: 1.4503x; 1.4503x over previous
#include <cuda_runtime.h>
#include <cuda_bf16.h>
#include <math.h>
#include <stdint.h>

#define NAC 20000
#define NBC 20000
#define NNC 40000
#define EC  150000

// ---------------------------------------------------------------------------
// Scratch (static device globals)
// ---------------------------------------------------------------------------
__device__ float g_h[NNC * 128];             // node features [a;b]
__device__ float g_feat_a[NAC * 640];        // q|kt0|vt0|kt1|vt1 for type a
__device__ float g_feat_b[NBC * 384];        // q|kt2|vt2 for type b
__device__ float g_wcat[3 * 128 * 1024];     // folded weights per layer
__device__ float g_bcat[3 * 1024];           // folded biases
__device__ __align__(16) __nv_bfloat16 g_wA[24 * 32768];  // split/swizzled wcat tiles
__device__ __align__(16) __nv_bfloat16 g_wO[6 * 32768];   // split/swizzled Wout tiles
__device__ float g_alpha[3 * EC * 4];        // CSR-ordered logits
__device__ float g_agg[NNC * 128];
__device__ float g_gout[NNC * 128];
__device__ int   g_deg[NNC + 1];
__device__ int   g_rowptr[NNC + 1];
__device__ int   g_cursor[NNC];
__device__ int   g_bsum[64];
__device__ int   g_cse[3 * EC];              // src | et<<29
__device__ float g_x1[NNC];
__device__ float g_score[NNC];
__device__ float g_stmp[NNC];

__device__ __forceinline__ float gelu_f(float x) {
    return 0.5f * x * (1.0f + erff(x * 0.7071067811865475f));
}
__device__ __forceinline__ uint32_t smem_u32(const void* p) {
    uint32_t a;
    asm("{ .reg .u64 t; cvta.to.shared.u64 t, %1; cvt.u32.u64 %0, t; }" : "=r"(a) : "l"(p));
    return a;
}
// mma.sync bf16: D(f32) += A(bf16 m16k16, row) * B(bf16 k16n8, col)
__device__ __forceinline__ void mma_bf16(float* c, const uint32_t* a, const uint32_t* b) {
    asm volatile(
        "mma.sync.aligned.m16n8k16.row.col.f32.bf16.bf16.f32 "
        "{%0,%1,%2,%3}, {%4,%5,%6,%7}, {%8,%9}, {%0,%1,%2,%3};"
        : "+f"(c[0]), "+f"(c[1]), "+f"(c[2]), "+f"(c[3])
        : "r"(a[0]), "r"(a[1]), "r"(a[2]), "r"(a[3]), "r"(b[0]), "r"(b[1]));
}
__device__ __forceinline__ void ldsm_x4(uint32_t* r, uint32_t addr) {
    asm volatile("ldmatrix.sync.aligned.m8n8.x4.shared.b16 {%0,%1,%2,%3}, [%4];"
                 : "=r"(r[0]), "=r"(r[1]), "=r"(r[2]), "=r"(r[3]) : "r"(addr));
}
// split 8 consecutive floats into packed bf16 hi (16B) and lo (16B)
__device__ __forceinline__ void split8(const float* f, uint4& hi, uint4& lo) {
    uint32_t h[4], l[4];
#pragma unroll
    for (int j = 0; j < 4; j++) {
        float f0 = f[2 * j], f1 = f[2 * j + 1];
        __nv_bfloat16 b0 = __float2bfloat16_rn(f0);
        __nv_bfloat16 b1 = __float2bfloat16_rn(f1);
        float r0 = f0 - __bfloat162float(b0);
        float r1 = f1 - __bfloat162float(b1);
        __nv_bfloat162 hh = __halves2bfloat162(b0, b1);
        __nv_bfloat162 ll = __halves2bfloat162(__float2bfloat16_rn(r0),
                                               __float2bfloat16_rn(r1));
        h[j] = *(uint32_t*)&hh;
        l[j] = *(uint32_t*)&ll;
    }
    hi = make_uint4(h[0], h[1], h[2], h[3]);
    lo = make_uint4(l[0], l[1], l[2], l[3]);
}

// ---------------------------------------------------------------------------
__global__ void k_copy_in(const float* __restrict__ xa, const float* __restrict__ xb,
                          float* __restrict__ h, int na128, int nb128) {
    int i = blockIdx.x * blockDim.x + threadIdx.x;
    if (i < na128) h[i] = xa[i];
    if (i < nb128) h[na128 + i] = xb[i];
}

// ---------------------------------------------------------------------------
// Fold relation transforms into GEMM weights (reused across layers).
// ---------------------------------------------------------------------------
__global__ void k_fold(const float* __restrict__ Wkqv, const float* __restrict__ bkqv,
                       const float* __restrict__ arel, const float* __restrict__ mrel,
                       float* __restrict__ wcat, float* __restrict__ bcat) {
    int idx = blockIdx.x * blockDim.x + threadIdx.x;
    const int TOT = 3 * 129 * 1024;
    if (idx >= TOT) return;
    int L = idx / (129 * 1024);
    int r = idx % (129 * 1024);
    int i = r / 1024;            // 0..128 (128 = bias row)
    int c = r % 1024;
    int type = (c >= 640) ? 1 : 0;
    int cc = c - (type ? 640 : 0);
    int part = cc >> 7, wi = cc & 127;
    const float* Wrow;
    if (i < 128) Wrow = Wkqv + ((size_t)(L * 2 + type) * 128 + i) * 384;
    else         Wrow = bkqv + (size_t)(L * 2 + type) * 384;
    float val;
    if (part == 0) {
        val = Wrow[128 + wi];                       // q part
    } else {
        int et, kv;
        if (type == 0) { et = (part - 1) >> 1; kv = (part - 1) & 1; }
        else           { et = 2;               kv = part - 1; }
        int h = wi >> 5, e = wi & 31;
        const float* rel = (kv ? mrel : arel) + ((size_t)(L * 3 + et) * 4 + h) * 1024 + e;
        const float* wsrc = Wrow + (kv ? 256 : 0) + h * 32;
        float s = 0.f;
#pragma unroll
        for (int d = 0; d < 32; d++) s += wsrc[d] * rel[d * 32];
        val = s;
    }
    if (i < 128) wcat[(size_t)L * 131072 + (size_t)i * 1024 + c] = val;
    else         bcat[L * 1024 + c] = val;
}

// ---------------------------------------------------------------------------
// Pre-split weights into bf16 hi/lo, [N][K] layout, XOR-swizzled rows.
// Blob per 128x128 tile (32768 bf16 = 64KB):
//   [chunk0: hi 8192, lo 8192][chunk1: hi, lo], row n (64 bf16 = 128B), swizzled.
// Tiles 0..23 from wcat (L*8 + colTile), 24..29 from Wout.
// ---------------------------------------------------------------------------
__global__ void k_prep(const float* __restrict__ wcat, const float* __restrict__ Wout,
                       __nv_bfloat16* __restrict__ wA, __nv_bfloat16* __restrict__ wO) {
    int idx = blockIdx.x * blockDim.x + threadIdx.x;
    const int PER = 16384;
    if (idx >= 30 * PER) return;
    int t = idx / PER, e = idx % PER;
    int k = e >> 7, n = e & 127;
    float v;
    __nv_bfloat16* dst;
    if (t < 24) {
        int L = t >> 3, c0 = (t & 7) << 7;
        v = wcat[(size_t)L * 131072 + (size_t)k * 1024 + c0 + n];
        dst = wA + (size_t)t * 32768;
    } else {
        v = Wout[(size_t)(t - 24) * 16384 + k * 128 + n];
        dst = wO + (size_t)(t - 24) * 32768;
    }
    __nv_bfloat16 hi = __float2bfloat16_rn(v);
    __nv_bfloat16 lo = __float2bfloat16_rn(v - __bfloat162float(hi));
    int chunk = k >> 6, kk = k & 63;
    int ksw = ((kk * 2) ^ ((n & 7) << 4)) >> 1;
    dst += chunk * 16384;
    dst[n * 64 + ksw] = hi;
    dst[8192 + n * 64 + ksw] = lo;
}

// ---------------------------------------------------------------------------
// Tensor-core bf16 (2-split, 3-MMA) GEMM:
//   C[M, 128*gridX] = act(A[M,128]) @ W + bias
// CTA = 128x128 tile; 256 threads = 8 warps (2 M x 4 N); BK=64, 2 chunks.
// Weights pre-split/swizzled in wblob (+blockIdx.x*32768 bf16).
// ---------------------------------------------------------------------------
#define SMEM_GEMM 65536
template <bool GELU_A>
__global__ void __launch_bounds__(256)
k_gemm_bf16(const float* __restrict__ A, int lda, int M,
            const __nv_bfloat16* __restrict__ wblob, const float* __restrict__ bias,
            float* __restrict__ C, int ldc) {
    extern __shared__ __align__(128) char smem[];
    const int AHI = 0, ALO = 16384, BHI = 32768;
    uint32_t sb = smem_u32(smem);
    int tid = threadIdx.x, lane = tid & 31, wid = tid >> 5;
    int warp_m = wid & 1, warp_n = wid >> 1;          // 2 x 4 warps
    int row0 = blockIdx.y << 7, col0 = blockIdx.x << 7;
    const __nv_bfloat16* blob = wblob + (size_t)blockIdx.x * 32768;

    float acc[4][4][4] = {};

    int lm = lane & 15;            // ldmatrix row within 16
    int lk = (lane >> 4) << 4;     // +16B for upper half-warp

    for (int chunk = 0; chunk < 2; chunk++) {
        // ---- A: load 128x64 fp32, optional gelu, bf16 hi/lo split, swizzled STS
#pragma unroll
        for (int it = 0; it < 4; it++) {
            int i = it * 256 + tid;            // 0..1023
            int m = i >> 3, kg = i & 7;        // 8 floats per thread-slot
            float f[8] = {};
            if (row0 + m < M) {
                const float* ap = A + (size_t)(row0 + m) * lda + chunk * 64 + kg * 8;
                *(float4*)&f[0] = *(const float4*)ap;
                *(float4*)&f[4] = *(const float4*)(ap + 4);
            }
            if (GELU_A) {
#pragma unroll
                for (int j = 0; j < 8; j++) f[j] = gelu_f(f[j]);
            }
            uint4 hi, lo;
            split8(f, hi, lo);
            int off = m * 128 + ((kg * 16) ^ ((m & 7) << 4));
            *(uint4*)(smem + AHI + off) = hi;
            *(uint4*)(smem + ALO + off) = lo;
        }
        // ---- B: linear copy of pre-swizzled blob chunk (hi 16KB + lo 16KB)
        {
            const float4* src = (const float4*)(blob + chunk * 16384);
            float4* dst = (float4*)(smem + BHI);
#pragma unroll
            for (int it = 0; it < 8; it++) dst[it * 256 + tid] = src[it * 256 + tid];
        }
        __syncthreads();

#pragma unroll
        for (int k16 = 0; k16 < 4; k16++) {
            int kb = k16 * 32 + lk;
            uint32_t bh[2][4], bl[2][4];
#pragma unroll
            for (int ntp = 0; ntp < 2; ntp++) {
                int n = warp_n * 32 + ntp * 16 + lm;
                int off = n * 128 + (kb ^ ((n & 7) << 4));
                ldsm_x4(bh[ntp], sb + BHI + off);
                ldsm_x4(bl[ntp], sb + BHI + 16384 + off);
            }
#pragma unroll
            for (int mt = 0; mt < 4; mt++) {
                int m = warp_m * 64 + mt * 16 + lm;
                int off = m * 128 + (kb ^ ((m & 7) << 4));
                uint32_t ah[4], al[4];
                ldsm_x4(ah, sb + AHI + off);
                ldsm_x4(al, sb + ALO + off);
#pragma unroll
                for (int nt = 0; nt < 4; nt++) {
                    uint32_t bfh[2] = {bh[nt >> 1][nt & 1], bh[nt >> 1][(nt & 1) + 2]};
                    uint32_t bfl[2] = {bl[nt >> 1][nt & 1], bl[nt >> 1][(nt & 1) + 2]};
                    mma_bf16(acc[mt][nt], ah, bfh);
                    mma_bf16(acc[mt][nt], ah, bfl);
                    mma_bf16(acc[mt][nt], al, bfh);
                }
            }
        }
        __syncthreads();
    }

    // ---- epilogue: fragment scatter + bias
    int crow = lane >> 2, ccol = (lane & 3) * 2;
#pragma unroll
    for (int nt = 0; nt < 4; nt++) {
        int n = col0 + warp_n * 32 + nt * 8 + ccol;
        float b0 = bias[n], b1 = bias[n + 1];
#pragma unroll
        for (int mt = 0; mt < 4; mt++) {
            int m = row0 + warp_m * 64 + mt * 16 + crow;
            if (m < M) {
                float2 o = make_float2(acc[mt][nt][0] + b0, acc[mt][nt][1] + b1);
                *(float2*)(C + (size_t)m * ldc + n) = o;
            }
            if (m + 8 < M) {
                float2 o = make_float2(acc[mt][nt][2] + b0, acc[mt][nt][3] + b1);
                *(float2*)(C + (size_t)(m + 8) * ldc + n) = o;
            }
        }
    }
}

// ---------------------------------------------------------------------------
// CSR build
// ---------------------------------------------------------------------------
__global__ void k_zero_deg(int* d, int n) {
    int i = blockIdx.x * blockDim.x + threadIdx.x;
    if (i < n) d[i] = 0;
}
__global__ void k_count(const int* __restrict__ aa, const int* __restrict__ ab,
                        const int* __restrict__ ba, int* __restrict__ deg, int E, int Na) {
    int i = blockIdx.x * blockDim.x + threadIdx.x;
    if (i >= 3 * E) return;
    int dst;
    if (i < E) dst = aa[E + i];
    else if (i < 2 * E) dst = ab[E + (i - E)] + Na;
    else dst = ba[E + (i - 2 * E)];
    atomicAdd(&deg[dst + 1], 1);
}
__global__ void k_scan1(const int* __restrict__ deg, int* __restrict__ rowptr,
                        int* __restrict__ bsum, int n) {
    __shared__ int buf[1024];
    int i = blockIdx.x * 1024 + threadIdx.x;
    int v = (i < n) ? deg[i] : 0;
    buf[threadIdx.x] = v;
    __syncthreads();
    for (int o = 1; o < 1024; o <<= 1) {
        int u = (threadIdx.x >= o) ? buf[threadIdx.x - o] : 0;
        __syncthreads();
        buf[threadIdx.x] += u;
        __syncthreads();
    }
    if (i < n) rowptr[i] = buf[threadIdx.x];
    if (threadIdx.x == 1023) bsum[blockIdx.x] = buf[1023];
}
__global__ void k_scan2(int* __restrict__ bsum, int nb) {
    __shared__ int s[64];
    int t = threadIdx.x;
    int v = (t < nb) ? bsum[t] : 0;
    s[t] = v;
    __syncthreads();
    for (int o = 1; o < 64; o <<= 1) {
        int u = (t >= o) ? s[t - o] : 0;
        __syncthreads();
        s[t] += u;
        __syncthreads();
    }
    if (t < nb) bsum[t] = s[t] - v;   // exclusive
}
__global__ void k_scan3(const int* __restrict__ bsum, int* __restrict__ rowptr,
                        int* __restrict__ cursor, int n, int N) {
    int i = blockIdx.x * blockDim.x + threadIdx.x;
    if (i >= n) return;
    int v = rowptr[i] + bsum[i >> 10];
    rowptr[i] = v;
    if (i < N) cursor[i] = v;
}
__global__ void k_fill(const int* __restrict__ aa, const int* __restrict__ ab,
                       const int* __restrict__ ba, int* __restrict__ cursor,
                       int* __restrict__ cse, int E, int Na) {
    int i = blockIdx.x * blockDim.x + threadIdx.x;
    if (i >= 3 * E) return;
    int src, dst, et;
    if (i < E)            { et = 0; src = aa[i]; dst = aa[E + i]; }
    else if (i < 2 * E)   { et = 1; int j = i - E;     src = ab[j]; dst = ab[E + j] + Na; }
    else                  { et = 2; int j = i - 2 * E; src = ba[j]; dst = ba[E + j]; }
    int pos = atomicAdd(&cursor[dst], 1);
    cse[pos] = src | (et << 29);
}

// ---------------------------------------------------------------------------
// Fused HGT edge softmax-aggregate. One warp per dst node.
// ---------------------------------------------------------------------------
__global__ void k_hgt_edges(const float* __restrict__ fa, const float* __restrict__ fb,
                            const int* __restrict__ rowptr, const int* __restrict__ cse,
                            const float* __restrict__ prelL,
                            float* __restrict__ alpha, float* __restrict__ agg,
                            int Na, int N) {
    __shared__ float sp[12];
    if (threadIdx.x < 12) sp[threadIdx.x] = prelL[threadIdx.x];
    __syncthreads();
    int warp = (blockIdx.x * blockDim.x + threadIdx.x) >> 5;
    int lane = threadIdx.x & 31;
    if (warp >= N) return;
    int n = warp;
    const float* qrow = (n < Na) ? (fa + (size_t)n * 640) : (fb + (size_t)(n - Na) * 384);
    float4 q4 = *(const float4*)(qrow + lane * 4);
    int h = lane >> 3;
    int beg = rowptr[n], end = rowptr[n + 1];
    float mx = -INFINITY;
    for (int idx = beg; idx < end; idx++) {
        int p = cse[idx];
        int et = p >> 29, src = p & 0x1FFFFFFF;
        const float* kb = (et < 2) ? (fa + (size_t)src * 640 + 128 + (et << 8))
                                   : (fb + (size_t)src * 384 + 128);
        float4 k4 = *(const float4*)(kb + lane * 4);
        float s = q4.x * k4.x + q4.y * k4.y + q4.z * k4.z + q4.w * k4.w;
        s += __shfl_xor_sync(0xffffffffu, s, 1);
        s += __shfl_xor_sync(0xffffffffu, s, 2);
        s += __shfl_xor_sync(0xffffffffu, s, 4);
        float lg = s * sp[et * 4 + h] * 0.17677669529663687f;
        if ((lane & 7) == 0) alpha[(size_t)idx * 4 + h] = lg;
        mx = fmaxf(mx, lg);
    }
    float sum = 0.f;
    float4 acc = make_float4(0.f, 0.f, 0.f, 0.f);
    for (int idx = beg; idx < end; idx++) {
        int p = cse[idx];
        int et = p >> 29, src = p & 0x1FFFFFFF;
        const float* vb = (et < 2) ? (fa + (size_t)src * 640 + 256 + (et << 8))
                                   : (fb + (size_t)src * 384 + 256);
        float lg = alpha[(size_t)idx * 4 + h];
        float w = expf(lg - mx);
        sum += w;
        float4 v4 = *(const float4*)(vb + lane * 4);
        acc.x += w * v4.x; acc.y += w * v4.y; acc.z += w * v4.z; acc.w += w * v4.w;
    }
    float inv = 1.f / (sum + 1e-16f);
    acc.x *= inv; acc.y *= inv; acc.z *= inv; acc.w *= inv;
    *(float4*)(agg + (size_t)n * 128 + lane * 4) = acc;
}

// ---------------------------------------------------------------------------
// Epilogue: h = gelu( [LN]( s*g + (1-s)*h ) )
// ---------------------------------------------------------------------------
__global__ void k_epilogue(const float* __restrict__ g, float* __restrict__ h,
                           const float* __restrict__ skipv,
                           const float* __restrict__ lng, const float* __restrict__ lnb,
                           int doLN) {
    int n = blockIdx.x, t = threadIdx.x;
    float s = 1.0f / (1.0f + expf(-skipv[0]));
    size_t idx = (size_t)n * 128 + t;
    float v = s * g[idx] + (1.0f - s) * h[idx];
    if (doLN) {
        float sv = v, sq = v * v;
#pragma unroll
        for (int o = 16; o > 0; o >>= 1) {
            sv += __shfl_down_sync(0xffffffffu, sv, o);
            sq += __shfl_down_sync(0xffffffffu, sq, o);
        }
        __shared__ float s1[4], s2[4];
        int w = t >> 5;
        if ((t & 31) == 0) { s1[w] = sv; s2[w] = sq; }
        __syncthreads();
        float mu = (s1[0] + s1[1] + s1[2] + s1[3]) * 0.0078125f;
        float eq = (s2[0] + s2[1] + s2[2] + s2[3]) * 0.0078125f;
        float var = eq - mu * mu;
        v = (v - mu) * rsqrtf(var + 1e-5f) * lng[t] + lnb[t];
    }
    h[idx] = gelu_f(v);
}

// ---------------------------------------------------------------------------
// GAT scorer via CSR (+analytic self loops)
// ---------------------------------------------------------------------------
__global__ void k_x1(const float* __restrict__ h, const float* __restrict__ Wg,
                     float* __restrict__ x1, int N) {
    int gw = (blockIdx.x * blockDim.x + threadIdx.x) >> 5;
    int lane = threadIdx.x & 31;
    if (gw >= N) return;
    const float* row = h + (size_t)gw * 128;
    float v = row[lane] * Wg[lane] + row[32 + lane] * Wg[32 + lane]
            + row[64 + lane] * Wg[64 + lane] + row[96 + lane] * Wg[96 + lane];
    v += __shfl_down_sync(0xffffffffu, v, 16);
    v += __shfl_down_sync(0xffffffffu, v, 8);
    v += __shfl_down_sync(0xffffffffu, v, 4);
    v += __shfl_down_sync(0xffffffffu, v, 2);
    v += __shfl_down_sync(0xffffffffu, v, 1);
    if (lane == 0) x1[gw] = v;
}

__global__ void k_gat(const float* __restrict__ x1, const int* __restrict__ rowptr,
                      const int* __restrict__ cse, const float* __restrict__ as_,
                      const float* __restrict__ ad_, const float* __restrict__ bg,
                      float* __restrict__ score, int Na, int N) {
    int n = blockIdx.x * blockDim.x + threadIdx.x;
    if (n >= N) return;
    float a_s = as_[0], a_d = ad_[0];
    float xd = x1[n];
    float eself = xd * (a_s + a_d);
    eself = eself > 0.f ? eself : 0.2f * eself;
    float m = eself;
    int beg = rowptr[n], end = rowptr[n + 1];
    for (int i = beg; i < end; i++) {
        int p = cse[i];
        int src = (p & 0x1FFFFFFF) + (((p >> 29) == 2) ? Na : 0);
        float e = x1[src] * a_s + xd * a_d;
        e = e > 0.f ? e : 0.2f * e;
        m = fmaxf(m, e);
    }
    float w = expf(eself - m), s = w, num = w * xd;
    for (int i = beg; i < end; i++) {
        int p = cse[i];
        int src = (p & 0x1FFFFFFF) + (((p >> 29) == 2) ? Na : 0);
        float e = x1[src] * a_s + xd * a_d;
        e = e > 0.f ? e : 0.2f * e;
        float ww = expf(e - m);
        s += ww; num += ww * x1[src];
    }
    score[n] = num / (s + 1e-16f) + bg[0];
}

// ---------------------------------------------------------------------------
// Final: top-K=8, gated readout, 3-layer MLP, nan_to_num.
// ---------------------------------------------------------------------------
__global__ void k_final(const float* __restrict__ h, const float* __restrict__ score,
                        float* __restrict__ stmp,
                        const float* __restrict__ W1, const float* __restrict__ b1,
                        const float* __restrict__ W2, const float* __restrict__ b2,
                        const float* __restrict__ W3, const float* __restrict__ b3,
                        float* __restrict__ out, int N) {
    const float NEG_INF = __int_as_float(0xff800000);
    __shared__ float sred[256];
    __shared__ int   sidx[256];
    __shared__ float hp[1024];
    __shared__ int   perm[8];
    __shared__ float vals[8];
    __shared__ float v1[128];
    __shared__ float v2[64];
    int t = threadIdx.x;

    for (int i = t; i < N; i += 256) stmp[i] = score[i];
    __syncthreads();

    for (int k = 0; k < 8; k++) {
        float bv = NEG_INF; int bi = 0x7fffffff;
        for (int i = t; i < N; i += 256) {
            float v = stmp[i];
            if (v > bv || (v == bv && i < bi)) { bv = v; bi = i; }
        }
        sred[t] = bv; sidx[t] = bi;
        __syncthreads();
        for (int s = 128; s > 0; s >>= 1) {
            if (t < s) {
                if (sred[t + s] > sred[t] ||
                    (sred[t + s] == sred[t] && sidx[t + s] < sidx[t])) {
                    sred[t] = sred[t + s]; sidx[t] = sidx[t + s];
                }
            }
            __syncthreads();
        }
        if (t == 0) { perm[k] = sidx[0]; vals[k] = sred[0]; stmp[sidx[0]] = NEG_INF; }
        __syncthreads();
    }

    for (int i = t; i < 1024; i += 256) {
        int k = i >> 7, j = i & 127;
        hp[i] = h[(size_t)perm[k] * 128 + j] * tanhf(vals[k]);
    }
    __syncthreads();

    if (t < 128) {
        float acc = b1[t];
        for (int i = 0; i < 1024; i++) acc += hp[i] * W1[i * 128 + t];
        v1[t] = gelu_f(acc);
    }
    __syncthreads();
    if (t < 64) {
        float acc = b2[t];
        for (int i = 0; i < 128; i++) acc += v1[i] * W2[i * 64 + t];
        v2[t] = gelu_f(acc);
    }
    __syncthreads();
    if (t < 16) {
        float acc = b3[t];
        for (int i = 0; i < 64; i++) acc += v2[i] * W3[i * 16 + t];
        float r = gelu_f(acc);
        if (isnan(r)) r = 0.f;
        else if (isinf(r)) r = (r > 0.f) ? 3.4028234663852886e38f : -3.4028234663852886e38f;
        out[t] = r;
    }
}

// ---------------------------------------------------------------------------
static inline int cdiv(int a, int b) { return (a + b - 1) / b; }

extern "C" void kernel_launch(void* const* d_in, const int* in_sizes, int n_in,
                              void* d_out, int out_size) {
    const float* x_a   = (const float*)d_in[0];
    const float* x_b   = (const float*)d_in[1];
    const int*   ei_aa = (const int*)d_in[2];
    const int*   ei_ab = (const int*)d_in[3];
    const int*   ei_ba = (const int*)d_in[4];
    const float* Wkqv  = (const float*)d_in[5];
    const float* bkqv  = (const float*)d_in[6];
    const float* Wout  = (const float*)d_in[7];
    const float* bout  = (const float*)d_in[8];
    const float* skip  = (const float*)d_in[9];
    const float* arel  = (const float*)d_in[10];
    const float* mrel  = (const float*)d_in[11];
    const float* prel  = (const float*)d_in[12];
    const float* ln_g  = (const float*)d_in[13];
    const float* ln_b  = (const float*)d_in[14];
    const float* Wgat  = (const float*)d_in[15];
    const float* att_s = (const float*)d_in[16];
    const float* att_d = (const float*)d_in[17];
    const float* bgat  = (const float*)d_in[18];
    const float* W1    = (const float*)d_in[19];
    const float* b1    = (const float*)d_in[20];
    const float* W2    = (const float*)d_in[21];
    const float* b2    = (const float*)d_in[22];
    const float* W3    = (const float*)d_in[23];
    const float* b3    = (const float*)d_in[24];

    int Na = in_sizes[0] / 128;
    int Nb = in_sizes[1] / 128;
    int N  = Na + Nb;
    int E  = in_sizes[2] / 2;

    float *hbuf, *fa, *fb, *wcat, *bcat, *alphab, *aggb, *goutb, *x1b, *scoreb, *stmpb;
    __nv_bfloat16 *wAb, *wOb;
    int *degb, *rowptrb, *cursorb, *cseb, *bsumb;
    cudaGetSymbolAddress((void**)&hbuf, g_h);
    cudaGetSymbolAddress((void**)&fa, g_feat_a);
    cudaGetSymbolAddress((void**)&fb, g_feat_b);
    cudaGetSymbolAddress((void**)&wcat, g_wcat);
    cudaGetSymbolAddress((void**)&bcat, g_bcat);
    cudaGetSymbolAddress((void**)&wAb, g_wA);
    cudaGetSymbolAddress((void**)&wOb, g_wO);
    cudaGetSymbolAddress((void**)&alphab, g_alpha);
    cudaGetSymbolAddress((void**)&aggb, g_agg);
    cudaGetSymbolAddress((void**)&goutb, g_gout);
    cudaGetSymbolAddress((void**)&degb, g_deg);
    cudaGetSymbolAddress((void**)&rowptrb, g_rowptr);
    cudaGetSymbolAddress((void**)&cursorb, g_cursor);
    cudaGetSymbolAddress((void**)&cseb, g_cse);
    cudaGetSymbolAddress((void**)&bsumb, g_bsum);
    cudaGetSymbolAddress((void**)&x1b, g_x1);
    cudaGetSymbolAddress((void**)&scoreb, g_score);
    cudaGetSymbolAddress((void**)&stmpb, g_stmp);

    cudaFuncSetAttribute(k_gemm_bf16<false>, cudaFuncAttributeMaxDynamicSharedMemorySize, SMEM_GEMM);
    cudaFuncSetAttribute(k_gemm_bf16<true>,  cudaFuncAttributeMaxDynamicSharedMemorySize, SMEM_GEMM);

    // inputs + CSR build + weight folding/prep (reused across layers)
    {
        int tot = (Na > Nb ? Na : Nb) * 128;
        k_copy_in<<<cdiv(tot, 256), 256>>>(x_a, x_b, hbuf, Na * 128, Nb * 128);
    }
    int n1 = N + 1;
    int nb = cdiv(n1, 1024);
    k_zero_deg<<<cdiv(n1, 256), 256>>>(degb, n1);
    k_count<<<cdiv(3 * E, 256), 256>>>(ei_aa, ei_ab, ei_ba, degb, E, Na);
    k_scan1<<<nb, 1024>>>(degb, rowptrb, bsumb, n1);
    k_scan2<<<1, 64>>>(bsumb, nb);
    k_scan3<<<cdiv(n1, 256), 256>>>(bsumb, rowptrb, cursorb, n1, N);
    k_fill<<<cdiv(3 * E, 256), 256>>>(ei_aa, ei_ab, ei_ba, cursorb, cseb, E, Na);
    k_fold<<<cdiv(3 * 129 * 1024, 256), 256>>>(Wkqv, bkqv, arel, mrel, wcat, bcat);
    k_prep<<<cdiv(30 * 16384, 256), 256>>>(wcat, Wout, wAb, wOb);

    int mbA = cdiv(Na, 128), mbB = cdiv(Nb, 128);

    for (int L = 0; L < 3; L++) {
        // feature GEMMs (q + folded kt/vt), tensor-core bf16 2-split
        k_gemm_bf16<false><<<dim3(5, mbA), 256, SMEM_GEMM>>>(
            hbuf, 128, Na, wAb + (size_t)L * 8 * 32768, bcat + L * 1024, fa, 640);
        k_gemm_bf16<false><<<dim3(3, mbB), 256, SMEM_GEMM>>>(
            hbuf + (size_t)Na * 128, 128, Nb, wAb + ((size_t)L * 8 + 5) * 32768,
            bcat + L * 1024 + 640, fb, 384);
        // fused edge softmax-aggregate
        k_hgt_edges<<<cdiv(N * 32, 256), 256>>>(fa, fb, rowptrb, cseb,
            prel + L * 12, alphab, aggb, Na, N);
        // out GEMM with fused gelu-on-input
        for (int t = 0; t < 2; t++) {
            int Nt = t ? Nb : Na;
            size_t off = (size_t)(t ? Na : 0) * 128;
            k_gemm_bf16<true><<<dim3(1, cdiv(Nt, 128)), 256, SMEM_GEMM>>>(
                aggb + off, 128, Nt, wOb + (size_t)(L * 2 + t) * 32768,
                bout + (size_t)(L * 2 + t) * 128, goutb + off, 128);
        }
        for (int t = 0; t < 2; t++) {
            int Nt = t ? Nb : Na;
            size_t off = (size_t)(t ? Na : 0) * 128;
            k_epilogue<<<Nt, 128>>>(goutb + off, hbuf + off, skip + (L * 2 + t),
                                    ln_g + t * 128, ln_b + t * 128, (L == 0) ? 1 : 0);
        }
    }

    // GAT scorer + SAGPool + MLP
    k_x1<<<cdiv(N * 32, 256), 256>>>(hbuf, Wgat, x1b, N);
    k_gat<<<cdiv(N, 256), 256>>>(x1b, rowptrb, cseb, att_s, att_d, bgat, scoreb, Na, N);
    k_final<<<1, 256>>>(hbuf, scoreb, stmpb, W1, b1, W2, b2, W3, b3, (float*)d_out, N);
}

// round 6
// speedup vs baseline: 1.5239x; 1.0508x over previous
#include <cuda_runtime.h>
#include <cuda_bf16.h>
#include <math.h>
#include <stdint.h>

#define NAC 20000
#define NBC 20000
#define NNC 40000
#define EC  150000
#define MAXCAND 2048

// ---------------------------------------------------------------------------
// Scratch (static device globals)
// ---------------------------------------------------------------------------
__device__ float g_h[NNC * 128];             // node features [a;b]
__device__ float g_feat_a[NAC * 640];        // q|kt0|vt0|kt1|vt1 for type a
__device__ float g_feat_b[NBC * 384];        // q|kt2|vt2 for type b
__device__ float g_wcat[3 * 128 * 1024];     // folded weights per layer
__device__ float g_bcat[3 * 1024];           // folded biases
__device__ __align__(16) __nv_bfloat16 g_wA[24 * 32768];  // split/swizzled wcat tiles
__device__ __align__(16) __nv_bfloat16 g_wO[6 * 32768];   // split/swizzled Wout tiles
__device__ float g_agg[NNC * 128];
__device__ int   g_deg[NNC + 1];
__device__ int   g_rowptr[NNC + 1];
__device__ int   g_cursor[NNC];
__device__ int   g_bsum[64];
__device__ int   g_cse[3 * EC];              // src | et<<29
__device__ float g_x1[NNC];
__device__ float g_score[NNC];
__device__ float g_cval[MAXCAND];
__device__ int   g_cidx[MAXCAND];

__device__ __forceinline__ float gelu_f(float x) {
    return 0.5f * x * (1.0f + erff(x * 0.7071067811865475f));
}
__device__ __forceinline__ uint32_t smem_u32(const void* p) {
    uint32_t a;
    asm("{ .reg .u64 t; cvta.to.shared.u64 t, %1; cvt.u32.u64 %0, t; }" : "=r"(a) : "l"(p));
    return a;
}
// mma.sync bf16: D(f32) += A(bf16 m16k16, row) * B(bf16 k16n8, col)
__device__ __forceinline__ void mma_bf16(float* c, const uint32_t* a, const uint32_t* b) {
    asm volatile(
        "mma.sync.aligned.m16n8k16.row.col.f32.bf16.bf16.f32 "
        "{%0,%1,%2,%3}, {%4,%5,%6,%7}, {%8,%9}, {%0,%1,%2,%3};"
        : "+f"(c[0]), "+f"(c[1]), "+f"(c[2]), "+f"(c[3])
        : "r"(a[0]), "r"(a[1]), "r"(a[2]), "r"(a[3]), "r"(b[0]), "r"(b[1]));
}
__device__ __forceinline__ void ldsm_x4(uint32_t* r, uint32_t addr) {
    asm volatile("ldmatrix.sync.aligned.m8n8.x4.shared.b16 {%0,%1,%2,%3}, [%4];"
                 : "=r"(r[0]), "=r"(r[1]), "=r"(r[2]), "=r"(r[3]) : "r"(addr));
}
// split 8 consecutive floats into packed bf16 hi (16B) and lo (16B)
__device__ __forceinline__ void split8(const float* f, uint4& hi, uint4& lo) {
    uint32_t h[4], l[4];
#pragma unroll
    for (int j = 0; j < 4; j++) {
        float f0 = f[2 * j], f1 = f[2 * j + 1];
        __nv_bfloat16 b0 = __float2bfloat16_rn(f0);
        __nv_bfloat16 b1 = __float2bfloat16_rn(f1);
        float r0 = f0 - __bfloat162float(b0);
        float r1 = f1 - __bfloat162float(b1);
        __nv_bfloat162 hh = __halves2bfloat162(b0, b1);
        __nv_bfloat162 ll = __halves2bfloat162(__float2bfloat16_rn(r0),
                                               __float2bfloat16_rn(r1));
        h[j] = *(uint32_t*)&hh;
        l[j] = *(uint32_t*)&ll;
    }
    hi = make_uint4(h[0], h[1], h[2], h[3]);
    lo = make_uint4(l[0], l[1], l[2], l[3]);
}

// ---------------------------------------------------------------------------
__global__ void k_copy_in(const float* __restrict__ xa, const float* __restrict__ xb,
                          float* __restrict__ h, int na128, int nb128) {
    int i = blockIdx.x * blockDim.x + threadIdx.x;
    if (i < na128) h[i] = xa[i];
    if (i < nb128) h[na128 + i] = xb[i];
}

// ---------------------------------------------------------------------------
// Fold relation transforms into GEMM weights (reused across layers).
// ---------------------------------------------------------------------------
__global__ void k_fold(const float* __restrict__ Wkqv, const float* __restrict__ bkqv,
                       const float* __restrict__ arel, const float* __restrict__ mrel,
                       float* __restrict__ wcat, float* __restrict__ bcat) {
    int idx = blockIdx.x * blockDim.x + threadIdx.x;
    const int TOT = 3 * 129 * 1024;
    if (idx >= TOT) return;
    int L = idx / (129 * 1024);
    int r = idx % (129 * 1024);
    int i = r / 1024;            // 0..128 (128 = bias row)
    int c = r % 1024;
    int type = (c >= 640) ? 1 : 0;
    int cc = c - (type ? 640 : 0);
    int part = cc >> 7, wi = cc & 127;
    const float* Wrow;
    if (i < 128) Wrow = Wkqv + ((size_t)(L * 2 + type) * 128 + i) * 384;
    else         Wrow = bkqv + (size_t)(L * 2 + type) * 384;
    float val;
    if (part == 0) {
        val = Wrow[128 + wi];                       // q part
    } else {
        int et, kv;
        if (type == 0) { et = (part - 1) >> 1; kv = (part - 1) & 1; }
        else           { et = 2;               kv = part - 1; }
        int h = wi >> 5, e = wi & 31;
        const float* rel = (kv ? mrel : arel) + ((size_t)(L * 3 + et) * 4 + h) * 1024 + e;
        const float* wsrc = Wrow + (kv ? 256 : 0) + h * 32;
        float s = 0.f;
#pragma unroll
        for (int d = 0; d < 32; d++) s += wsrc[d] * rel[d * 32];
        val = s;
    }
    if (i < 128) wcat[(size_t)L * 131072 + (size_t)i * 1024 + c] = val;
    else         bcat[L * 1024 + c] = val;
}

// ---------------------------------------------------------------------------
// Pre-split weights into bf16 hi/lo, [N][K] layout, XOR-swizzled rows.
// ---------------------------------------------------------------------------
__global__ void k_prep(const float* __restrict__ wcat, const float* __restrict__ Wout,
                       __nv_bfloat16* __restrict__ wA, __nv_bfloat16* __restrict__ wO) {
    int idx = blockIdx.x * blockDim.x + threadIdx.x;
    const int PER = 16384;
    if (idx >= 30 * PER) return;
    int t = idx / PER, e = idx % PER;
    int k = e >> 7, n = e & 127;
    float v;
    __nv_bfloat16* dst;
    if (t < 24) {
        int L = t >> 3, c0 = (t & 7) << 7;
        v = wcat[(size_t)L * 131072 + (size_t)k * 1024 + c0 + n];
        dst = wA + (size_t)t * 32768;
    } else {
        v = Wout[(size_t)(t - 24) * 16384 + k * 128 + n];
        dst = wO + (size_t)(t - 24) * 32768;
    }
    __nv_bfloat16 hi = __float2bfloat16_rn(v);
    __nv_bfloat16 lo = __float2bfloat16_rn(v - __bfloat162float(hi));
    int chunk = k >> 6, kk = k & 63;
    int ksw = ((kk * 2) ^ ((n & 7) << 4)) >> 1;
    dst += chunk * 16384;
    dst[n * 64 + ksw] = hi;
    dst[8192 + n * 64 + ksw] = lo;
}

// ---------------------------------------------------------------------------
// Tensor-core bf16 (2-split, 3-MMA) GEMM with optional fused epilogue.
// EPI=0: C = A@W + bias.
// EPI=1: C = gelu( s*(A@W+bias) + (1-s)*C )           (skip mix, in/out C)
// EPI=2: C = gelu( LN( s*(A@W+bias) + (1-s)*C ) )     (layer 0)
// CTA = 128x128 tile; 256 threads = 8 warps (2 M x 4 N); BK=64, 2 chunks.
// ---------------------------------------------------------------------------
#define SMEM_GEMM 65536
template <bool GELU_A, int EPI>
__global__ void __launch_bounds__(256)
k_gemm_bf16(const float* __restrict__ A, int lda, int M,
            const __nv_bfloat16* __restrict__ wblob, const float* __restrict__ bias,
            float* __restrict__ C, int ldc,
            const float* __restrict__ skipv,
            const float* __restrict__ lng, const float* __restrict__ lnb) {
    extern __shared__ __align__(128) char smem[];
    const int AHI = 0, ALO = 16384, BHI = 32768;
    uint32_t sb = smem_u32(smem);
    int tid = threadIdx.x, lane = tid & 31, wid = tid >> 5;
    int warp_m = wid & 1, warp_n = wid >> 1;          // 2 x 4 warps
    int row0 = blockIdx.y << 7, col0 = blockIdx.x << 7;
    const __nv_bfloat16* blob = wblob + (size_t)blockIdx.x * 32768;

    float acc[4][4][4] = {};

    int lm = lane & 15;            // ldmatrix row within 16
    int lk = (lane >> 4) << 4;     // +16B for upper half-warp

    for (int chunk = 0; chunk < 2; chunk++) {
        // ---- A: load 128x64 fp32, optional gelu, bf16 hi/lo split, swizzled STS
#pragma unroll
        for (int it = 0; it < 4; it++) {
            int i = it * 256 + tid;            // 0..1023
            int m = i >> 3, kg = i & 7;        // 8 floats per thread-slot
            float f[8] = {};
            if (row0 + m < M) {
                const float* ap = A + (size_t)(row0 + m) * lda + chunk * 64 + kg * 8;
                *(float4*)&f[0] = *(const float4*)ap;
                *(float4*)&f[4] = *(const float4*)(ap + 4);
            }
            if (GELU_A) {
#pragma unroll
                for (int j = 0; j < 8; j++) f[j] = gelu_f(f[j]);
            }
            uint4 hi, lo;
            split8(f, hi, lo);
            int off = m * 128 + ((kg * 16) ^ ((m & 7) << 4));
            *(uint4*)(smem + AHI + off) = hi;
            *(uint4*)(smem + ALO + off) = lo;
        }
        // ---- B: linear copy of pre-swizzled blob chunk (hi 16KB + lo 16KB)
        {
            const float4* src = (const float4*)(blob + chunk * 16384);
            float4* dst = (float4*)(smem + BHI);
#pragma unroll
            for (int it = 0; it < 8; it++) dst[it * 256 + tid] = src[it * 256 + tid];
        }
        __syncthreads();

#pragma unroll
        for (int k16 = 0; k16 < 4; k16++) {
            int kb = k16 * 32 + lk;
            uint32_t bh[2][4], bl[2][4];
#pragma unroll
            for (int ntp = 0; ntp < 2; ntp++) {
                int n = warp_n * 32 + ntp * 16 + lm;
                int off = n * 128 + (kb ^ ((n & 7) << 4));
                ldsm_x4(bh[ntp], sb + BHI + off);
                ldsm_x4(bl[ntp], sb + BHI + 16384 + off);
            }
#pragma unroll
            for (int mt = 0; mt < 4; mt++) {
                int m = warp_m * 64 + mt * 16 + lm;
                int off = m * 128 + (kb ^ ((m & 7) << 4));
                uint32_t ah[4], al[4];
                ldsm_x4(ah, sb + AHI + off);
                ldsm_x4(al, sb + ALO + off);
#pragma unroll
                for (int nt = 0; nt < 4; nt++) {
                    uint32_t bfh[2] = {bh[nt >> 1][nt & 1], bh[nt >> 1][(nt & 1) + 2]};
                    uint32_t bfl[2] = {bl[nt >> 1][nt & 1], bl[nt >> 1][(nt & 1) + 2]};
                    mma_bf16(acc[mt][nt], ah, bfh);
                    mma_bf16(acc[mt][nt], ah, bfl);
                    mma_bf16(acc[mt][nt], al, bfh);
                }
            }
        }
        __syncthreads();
    }

    int crow = lane >> 2, ccol = (lane & 3) * 2;
    if (EPI == 0) {
        // ---- plain store + bias
#pragma unroll
        for (int nt = 0; nt < 4; nt++) {
            int n = col0 + warp_n * 32 + nt * 8 + ccol;
            float b0 = bias[n], b1 = bias[n + 1];
#pragma unroll
            for (int mt = 0; mt < 4; mt++) {
                int m = row0 + warp_m * 64 + mt * 16 + crow;
                if (m < M) {
                    float2 o = make_float2(acc[mt][nt][0] + b0, acc[mt][nt][1] + b1);
                    *(float2*)(C + (size_t)m * ldc + n) = o;
                }
                if (m + 8 < M) {
                    float2 o = make_float2(acc[mt][nt][2] + b0, acc[mt][nt][3] + b1);
                    *(float2*)(C + (size_t)(m + 8) * ldc + n) = o;
                }
            }
        }
    } else {
        // ---- fused: skip mix (in place into acc)
        float sg = 1.f / (1.f + expf(-skipv[0]));
#pragma unroll
        for (int nt = 0; nt < 4; nt++) {
            int n = col0 + warp_n * 32 + nt * 8 + ccol;
            float b0 = bias[n], b1 = bias[n + 1];
#pragma unroll
            for (int mt = 0; mt < 4; mt++) {
                int m = row0 + warp_m * 64 + mt * 16 + crow;
                if (m < M) {
                    float2 h0 = *(const float2*)(C + (size_t)m * ldc + n);
                    acc[mt][nt][0] = sg * (acc[mt][nt][0] + b0) + (1.f - sg) * h0.x;
                    acc[mt][nt][1] = sg * (acc[mt][nt][1] + b1) + (1.f - sg) * h0.y;
                }
                if (m + 8 < M) {
                    float2 h1 = *(const float2*)(C + (size_t)(m + 8) * ldc + n);
                    acc[mt][nt][2] = sg * (acc[mt][nt][2] + b0) + (1.f - sg) * h1.x;
                    acc[mt][nt][3] = sg * (acc[mt][nt][3] + b1) + (1.f - sg) * h1.y;
                }
            }
        }
        if (EPI == 2) {
            // ---- LN stats across the 128-col row (4 N-warps cooperate)
            float* ssum = (float*)smem;
            float* ssq  = ssum + 128;
            if (tid < 128) { ssum[tid] = 0.f; ssq[tid] = 0.f; }
            __syncthreads();
#pragma unroll
            for (int mt = 0; mt < 4; mt++) {
#pragma unroll
                for (int half = 0; half < 2; half++) {
                    float p = 0.f, q = 0.f;
#pragma unroll
                    for (int nt = 0; nt < 4; nt++) {
                        float v0 = acc[mt][nt][half * 2];
                        float v1 = acc[mt][nt][half * 2 + 1];
                        p += v0 + v1; q += v0 * v0 + v1 * v1;
                    }
                    p += __shfl_xor_sync(~0u, p, 1); q += __shfl_xor_sync(~0u, q, 1);
                    p += __shfl_xor_sync(~0u, p, 2); q += __shfl_xor_sync(~0u, q, 2);
                    if ((lane & 3) == 0) {
                        int row = warp_m * 64 + mt * 16 + half * 8 + crow;
                        atomicAdd(&ssum[row], p);
                        atomicAdd(&ssq[row], q);
                    }
                }
            }
            __syncthreads();
#pragma unroll
            for (int mt = 0; mt < 4; mt++) {
                int r0 = warp_m * 64 + mt * 16 + crow;
                float mu0 = ssum[r0] * 0.0078125f;
                float rs0 = rsqrtf(ssq[r0] * 0.0078125f - mu0 * mu0 + 1e-5f);
                float mu1 = ssum[r0 + 8] * 0.0078125f;
                float rs1 = rsqrtf(ssq[r0 + 8] * 0.0078125f - mu1 * mu1 + 1e-5f);
                int m = row0 + r0;
#pragma unroll
                for (int nt = 0; nt < 4; nt++) {
                    int n = col0 + warp_n * 32 + nt * 8 + ccol;
                    float g0 = lng[n], g1 = lng[n + 1];
                    float e0 = lnb[n], e1 = lnb[n + 1];
                    if (m < M) {
                        float2 o;
                        o.x = gelu_f((acc[mt][nt][0] - mu0) * rs0 * g0 + e0);
                        o.y = gelu_f((acc[mt][nt][1] - mu0) * rs0 * g1 + e1);
                        *(float2*)(C + (size_t)m * ldc + n) = o;
                    }
                    if (m + 8 < M) {
                        float2 o;
                        o.x = gelu_f((acc[mt][nt][2] - mu1) * rs1 * g0 + e0);
                        o.y = gelu_f((acc[mt][nt][3] - mu1) * rs1 * g1 + e1);
                        *(float2*)(C + (size_t)(m + 8) * ldc + n) = o;
                    }
                }
            }
        } else {
            // EPI == 1: gelu + store
#pragma unroll
            for (int nt = 0; nt < 4; nt++) {
                int n = col0 + warp_n * 32 + nt * 8 + ccol;
#pragma unroll
                for (int mt = 0; mt < 4; mt++) {
                    int m = row0 + warp_m * 64 + mt * 16 + crow;
                    if (m < M) {
                        float2 o = make_float2(gelu_f(acc[mt][nt][0]),
                                               gelu_f(acc[mt][nt][1]));
                        *(float2*)(C + (size_t)m * ldc + n) = o;
                    }
                    if (m + 8 < M) {
                        float2 o = make_float2(gelu_f(acc[mt][nt][2]),
                                               gelu_f(acc[mt][nt][3]));
                        *(float2*)(C + (size_t)(m + 8) * ldc + n) = o;
                    }
                }
            }
        }
    }
}

// ---------------------------------------------------------------------------
// CSR build
// ---------------------------------------------------------------------------
__global__ void k_zero_deg(int* d, int n) {
    int i = blockIdx.x * blockDim.x + threadIdx.x;
    if (i < n) d[i] = 0;
}
__global__ void k_count(const int* __restrict__ aa, const int* __restrict__ ab,
                        const int* __restrict__ ba, int* __restrict__ deg, int E, int Na) {
    int i = blockIdx.x * blockDim.x + threadIdx.x;
    if (i >= 3 * E) return;
    int dst;
    if (i < E) dst = aa[E + i];
    else if (i < 2 * E) dst = ab[E + (i - E)] + Na;
    else dst = ba[E + (i - 2 * E)];
    atomicAdd(&deg[dst + 1], 1);
}
__global__ void k_scan1(const int* __restrict__ deg, int* __restrict__ rowptr,
                        int* __restrict__ bsum, int n) {
    __shared__ int buf[1024];
    int i = blockIdx.x * 1024 + threadIdx.x;
    int v = (i < n) ? deg[i] : 0;
    buf[threadIdx.x] = v;
    __syncthreads();
    for (int o = 1; o < 1024; o <<= 1) {
        int u = (threadIdx.x >= o) ? buf[threadIdx.x - o] : 0;
        __syncthreads();
        buf[threadIdx.x] += u;
        __syncthreads();
    }
    if (i < n) rowptr[i] = buf[threadIdx.x];
    if (threadIdx.x == 1023) bsum[blockIdx.x] = buf[1023];
}
__global__ void k_scan2(int* __restrict__ bsum, int nb) {
    __shared__ int s[64];
    int t = threadIdx.x;
    int v = (t < nb) ? bsum[t] : 0;
    s[t] = v;
    __syncthreads();
    for (int o = 1; o < 64; o <<= 1) {
        int u = (t >= o) ? s[t - o] : 0;
        __syncthreads();
        s[t] += u;
        __syncthreads();
    }
    if (t < nb) bsum[t] = s[t] - v;   // exclusive
}
__global__ void k_scan3(const int* __restrict__ bsum, int* __restrict__ rowptr,
                        int* __restrict__ cursor, int n, int N) {
    int i = blockIdx.x * blockDim.x + threadIdx.x;
    if (i >= n) return;
    int v = rowptr[i] + bsum[i >> 10];
    rowptr[i] = v;
    if (i < N) cursor[i] = v;
}
__global__ void k_fill(const int* __restrict__ aa, const int* __restrict__ ab,
                       const int* __restrict__ ba, int* __restrict__ cursor,
                       int* __restrict__ cse, int E, int Na) {
    int i = blockIdx.x * blockDim.x + threadIdx.x;
    if (i >= 3 * E) return;
    int src, dst, et;
    if (i < E)            { et = 0; src = aa[i]; dst = aa[E + i]; }
    else if (i < 2 * E)   { et = 1; int j = i - E;     src = ab[j]; dst = ab[E + j] + Na; }
    else                  { et = 2; int j = i - 2 * E; src = ba[j]; dst = ba[E + j]; }
    int pos = atomicAdd(&cursor[dst], 1);
    cse[pos] = src | (et << 29);
}

// ---------------------------------------------------------------------------
// Fused HGT edge online-softmax aggregate. One warp per dst node. Single pass.
// ---------------------------------------------------------------------------
__global__ void k_hgt_edges(const float* __restrict__ fa, const float* __restrict__ fb,
                            const int* __restrict__ rowptr, const int* __restrict__ cse,
                            const float* __restrict__ prelL,
                            float* __restrict__ agg, int Na, int N) {
    __shared__ float sp[12];
    if (threadIdx.x < 12) sp[threadIdx.x] = prelL[threadIdx.x];
    __syncthreads();
    int warp = (blockIdx.x * blockDim.x + threadIdx.x) >> 5;
    int lane = threadIdx.x & 31;
    if (warp >= N) return;
    int n = warp;
    const float* qrow = (n < Na) ? (fa + (size_t)n * 640) : (fb + (size_t)(n - Na) * 384);
    float4 q4 = *(const float4*)(qrow + lane * 4);
    int h = lane >> 3;
    int beg = rowptr[n], end = rowptr[n + 1];

    float mx = -INFINITY, sum = 0.f;
    float4 acc = make_float4(0.f, 0.f, 0.f, 0.f);

    int idx = beg;
    int p = 0;
    float4 k4 = {}, v4 = {};
    if (idx < end) {
        p = cse[idx];
        int et = p >> 29, src = p & 0x1FFFFFFF;
        const float* base = (et < 2) ? (fa + (size_t)src * 640 + 128 + (et << 8))
                                     : (fb + (size_t)src * 384 + 128);
        k4 = *(const float4*)(base + lane * 4);
        v4 = *(const float4*)(base + 128 + lane * 4);
    }
    while (idx < end) {
        int pn = 0;
        float4 k4n = {}, v4n = {};
        if (idx + 1 < end) {
            pn = cse[idx + 1];
            int etn = pn >> 29, srcn = pn & 0x1FFFFFFF;
            const float* basen = (etn < 2) ? (fa + (size_t)srcn * 640 + 128 + (etn << 8))
                                           : (fb + (size_t)srcn * 384 + 128);
            k4n = *(const float4*)(basen + lane * 4);
            v4n = *(const float4*)(basen + 128 + lane * 4);
        }
        int et = p >> 29;
        float s = q4.x * k4.x + q4.y * k4.y + q4.z * k4.z + q4.w * k4.w;
        s += __shfl_xor_sync(0xffffffffu, s, 1);
        s += __shfl_xor_sync(0xffffffffu, s, 2);
        s += __shfl_xor_sync(0xffffffffu, s, 4);
        float lg = s * sp[et * 4 + h] * 0.17677669529663687f;  // /sqrt(32)
        float mnew = fmaxf(mx, lg);
        float corr = expf(mx - mnew);    // 0 on first edge (mx=-inf)
        float w = expf(lg - mnew);
        sum = sum * corr + w;
        acc.x = acc.x * corr + w * v4.x;
        acc.y = acc.y * corr + w * v4.y;
        acc.z = acc.z * corr + w * v4.z;
        acc.w = acc.w * corr + w * v4.w;
        mx = mnew;
        p = pn; k4 = k4n; v4 = v4n; idx++;
    }
    float inv = 1.f / (sum + 1e-16f);
    acc.x *= inv; acc.y *= inv; acc.z *= inv; acc.w *= inv;
    *(float4*)(agg + (size_t)n * 128 + lane * 4) = acc;
}

// ---------------------------------------------------------------------------
// GAT scorer via CSR (+analytic self loops), online softmax, one pass
// ---------------------------------------------------------------------------
__global__ void k_x1(const float* __restrict__ h, const float* __restrict__ Wg,
                     float* __restrict__ x1, int N) {
    int gw = (blockIdx.x * blockDim.x + threadIdx.x) >> 5;
    int lane = threadIdx.x & 31;
    if (gw >= N) return;
    const float* row = h + (size_t)gw * 128;
    float v = row[lane] * Wg[lane] + row[32 + lane] * Wg[32 + lane]
            + row[64 + lane] * Wg[64 + lane] + row[96 + lane] * Wg[96 + lane];
    v += __shfl_down_sync(0xffffffffu, v, 16);
    v += __shfl_down_sync(0xffffffffu, v, 8);
    v += __shfl_down_sync(0xffffffffu, v, 4);
    v += __shfl_down_sync(0xffffffffu, v, 2);
    v += __shfl_down_sync(0xffffffffu, v, 1);
    if (lane == 0) x1[gw] = v;
}

__global__ void k_gat(const float* __restrict__ x1, const int* __restrict__ rowptr,
                      const int* __restrict__ cse, const float* __restrict__ as_,
                      const float* __restrict__ ad_, const float* __restrict__ bg,
                      float* __restrict__ score, int Na, int N) {
    int n = blockIdx.x * blockDim.x + threadIdx.x;
    if (n >= N) return;
    float a_s = as_[0], a_d = ad_[0];
    float xd = x1[n];
    float eself = xd * (a_s + a_d);
    eself = eself > 0.f ? eself : 0.2f * eself;
    float m = eself, sum = 1.f, num = xd;    // self loop: w=exp(0)=1
    int beg = rowptr[n], end = rowptr[n + 1];
    for (int i = beg; i < end; i++) {
        int p = cse[i];
        int src = (p & 0x1FFFFFFF) + (((p >> 29) == 2) ? Na : 0);
        float xs = x1[src];
        float e = xs * a_s + xd * a_d;
        e = e > 0.f ? e : 0.2f * e;
        float mnew = fmaxf(m, e);
        float corr = expf(m - mnew);
        float w = expf(e - mnew);
        sum = sum * corr + w;
        num = num * corr + w * xs;
        m = mnew;
    }
    score[n] = num / (sum + 1e-16f) + bg[0];
}

// ---------------------------------------------------------------------------
// Top-K prepass: each block emits its local top-8 (val desc, idx asc)
// ---------------------------------------------------------------------------
__global__ void k_topk(const float* __restrict__ score, float* __restrict__ cval,
                       int* __restrict__ cidx, int N) {
    const float NEG_INF = __int_as_float(0xff800000);
    __shared__ float sval[256];
    __shared__ int   sida[256];
    __shared__ float sred[256];
    __shared__ int   sidr[256];
    int t = threadIdx.x;
    int i = blockIdx.x * 256 + t;
    sval[t] = (i < N) ? score[i] : NEG_INF;
    sida[t] = (i < N) ? i : 0x7fffffff;
    __syncthreads();
    for (int k = 0; k < 8; k++) {
        sred[t] = sval[t]; sidr[t] = sida[t];
        __syncthreads();
        for (int s = 128; s > 0; s >>= 1) {
            if (t < s) {
                if (sred[t + s] > sred[t] ||
                    (sred[t + s] == sred[t] && sidr[t + s] < sidr[t])) {
                    sred[t] = sred[t + s]; sidr[t] = sidr[t + s];
                }
            }
            __syncthreads();
        }
        int win = sidr[0];
        if (t == 0) {
            cval[blockIdx.x * 8 + k] = sred[0];
            cidx[blockIdx.x * 8 + k] = win;
        }
        if (sida[t] == win) sval[t] = NEG_INF;
        __syncthreads();
    }
}

// ---------------------------------------------------------------------------
// Final: global top-8 from candidates, gated readout, 3-layer MLP, nan_to_num.
// ---------------------------------------------------------------------------
__global__ void k_final(const float* __restrict__ h,
                        const float* __restrict__ cval, const int* __restrict__ cidx,
                        int ncand,
                        const float* __restrict__ W1, const float* __restrict__ b1,
                        const float* __restrict__ W2, const float* __restrict__ b2,
                        const float* __restrict__ W3, const float* __restrict__ b3,
                        float* __restrict__ out) {
    const float NEG_INF = __int_as_float(0xff800000);
    __shared__ float cv[MAXCAND];
    __shared__ int   ci[MAXCAND];
    __shared__ float sred[256];
    __shared__ int   sidx[256];
    __shared__ float hp[1024];
    __shared__ int   perm[8];
    __shared__ float vals[8];
    __shared__ float v1[128];
    __shared__ float v2[64];
    int t = threadIdx.x;

    for (int i = t; i < MAXCAND; i += 256) {
        cv[i] = (i < ncand) ? cval[i] : NEG_INF;
        ci[i] = (i < ncand) ? cidx[i] : 0x7fffffff;
    }
    __syncthreads();

    for (int k = 0; k < 8; k++) {
        float bv = NEG_INF; int bi = 0x7fffffff;
        for (int i = t; i < MAXCAND; i += 256) {
            float v = cv[i];
            if (v > bv || (v == bv && ci[i] < bi)) { bv = v; bi = ci[i]; }
        }
        sred[t] = bv; sidx[t] = bi;
        __syncthreads();
        for (int s = 128; s > 0; s >>= 1) {
            if (t < s) {
                if (sred[t + s] > sred[t] ||
                    (sred[t + s] == sred[t] && sidx[t + s] < sidx[t])) {
                    sred[t] = sred[t + s]; sidx[t] = sidx[t + s];
                }
            }
            __syncthreads();
        }
        int win = sidx[0];
        if (t == 0) { perm[k] = win; vals[k] = sred[0]; }
        for (int i = t; i < MAXCAND; i += 256)
            if (ci[i] == win) cv[i] = NEG_INF;
        __syncthreads();
    }

    for (int i = t; i < 1024; i += 256) {
        int k = i >> 7, j = i & 127;
        hp[i] = h[(size_t)perm[k] * 128 + j] * tanhf(vals[k]);
    }
    __syncthreads();

    if (t < 128) {
        float acc = b1[t];
        for (int i = 0; i < 1024; i++) acc += hp[i] * W1[i * 128 + t];
        v1[t] = gelu_f(acc);
    }
    __syncthreads();
    if (t < 64) {
        float acc = b2[t];
        for (int i = 0; i < 128; i++) acc += v1[i] * W2[i * 64 + t];
        v2[t] = gelu_f(acc);
    }
    __syncthreads();
    if (t < 16) {
        float acc = b3[t];
        for (int i = 0; i < 64; i++) acc += v2[i] * W3[i * 16 + t];
        float r = gelu_f(acc);
        if (isnan(r)) r = 0.f;
        else if (isinf(r)) r = (r > 0.f) ? 3.4028234663852886e38f : -3.4028234663852886e38f;
        out[t] = r;
    }
}

// ---------------------------------------------------------------------------
static inline int cdiv(int a, int b) { return (a + b - 1) / b; }

extern "C" void kernel_launch(void* const* d_in, const int* in_sizes, int n_in,
                              void* d_out, int out_size) {
    const float* x_a   = (const float*)d_in[0];
    const float* x_b   = (const float*)d_in[1];
    const int*   ei_aa = (const int*)d_in[2];
    const int*   ei_ab = (const int*)d_in[3];
    const int*   ei_ba = (const int*)d_in[4];
    const float* Wkqv  = (const float*)d_in[5];
    const float* bkqv  = (const float*)d_in[6];
    const float* Wout  = (const float*)d_in[7];
    const float* bout  = (const float*)d_in[8];
    const float* skip  = (const float*)d_in[9];
    const float* arel  = (const float*)d_in[10];
    const float* mrel  = (const float*)d_in[11];
    const float* prel  = (const float*)d_in[12];
    const float* ln_g  = (const float*)d_in[13];
    const float* ln_b  = (const float*)d_in[14];
    const float* Wgat  = (const float*)d_in[15];
    const float* att_s = (const float*)d_in[16];
    const float* att_d = (const float*)d_in[17];
    const float* bgat  = (const float*)d_in[18];
    const float* W1    = (const float*)d_in[19];
    const float* b1    = (const float*)d_in[20];
    const float* W2    = (const float*)d_in[21];
    const float* b2    = (const float*)d_in[22];
    const float* W3    = (const float*)d_in[23];
    const float* b3    = (const float*)d_in[24];

    int Na = in_sizes[0] / 128;
    int Nb = in_sizes[1] / 128;
    int N  = Na + Nb;
    int E  = in_sizes[2] / 2;

    float *hbuf, *fa, *fb, *wcat, *bcat, *aggb, *x1b, *scoreb, *cvalb;
    __nv_bfloat16 *wAb, *wOb;
    int *degb, *rowptrb, *cursorb, *cseb, *bsumb, *cidxb;
    cudaGetSymbolAddress((void**)&hbuf, g_h);
    cudaGetSymbolAddress((void**)&fa, g_feat_a);
    cudaGetSymbolAddress((void**)&fb, g_feat_b);
    cudaGetSymbolAddress((void**)&wcat, g_wcat);
    cudaGetSymbolAddress((void**)&bcat, g_bcat);
    cudaGetSymbolAddress((void**)&wAb, g_wA);
    cudaGetSymbolAddress((void**)&wOb, g_wO);
    cudaGetSymbolAddress((void**)&aggb, g_agg);
    cudaGetSymbolAddress((void**)&degb, g_deg);
    cudaGetSymbolAddress((void**)&rowptrb, g_rowptr);
    cudaGetSymbolAddress((void**)&cursorb, g_cursor);
    cudaGetSymbolAddress((void**)&cseb, g_cse);
    cudaGetSymbolAddress((void**)&bsumb, g_bsum);
    cudaGetSymbolAddress((void**)&x1b, g_x1);
    cudaGetSymbolAddress((void**)&scoreb, g_score);
    cudaGetSymbolAddress((void**)&cvalb, g_cval);
    cudaGetSymbolAddress((void**)&cidxb, g_cidx);

    cudaFuncSetAttribute(k_gemm_bf16<false, 0>, cudaFuncAttributeMaxDynamicSharedMemorySize, SMEM_GEMM);
    cudaFuncSetAttribute(k_gemm_bf16<true, 1>,  cudaFuncAttributeMaxDynamicSharedMemorySize, SMEM_GEMM);
    cudaFuncSetAttribute(k_gemm_bf16<true, 2>,  cudaFuncAttributeMaxDynamicSharedMemorySize, SMEM_GEMM);

    // inputs + CSR build + weight folding/prep (reused across layers)
    {
        int tot = (Na > Nb ? Na : Nb) * 128;
        k_copy_in<<<cdiv(tot, 256), 256>>>(x_a, x_b, hbuf, Na * 128, Nb * 128);
    }
    int n1 = N + 1;
    int nb = cdiv(n1, 1024);
    k_zero_deg<<<cdiv(n1, 256), 256>>>(degb, n1);
    k_count<<<cdiv(3 * E, 256), 256>>>(ei_aa, ei_ab, ei_ba, degb, E, Na);
    k_scan1<<<nb, 1024>>>(degb, rowptrb, bsumb, n1);
    k_scan2<<<1, 64>>>(bsumb, nb);
    k_scan3<<<cdiv(n1, 256), 256>>>(bsumb, rowptrb, cursorb, n1, N);
    k_fill<<<cdiv(3 * E, 256), 256>>>(ei_aa, ei_ab, ei_ba, cursorb, cseb, E, Na);
    k_fold<<<cdiv(3 * 129 * 1024, 256), 256>>>(Wkqv, bkqv, arel, mrel, wcat, bcat);
    k_prep<<<cdiv(30 * 16384, 256), 256>>>(wcat, Wout, wAb, wOb);

    int mbA = cdiv(Na, 128), mbB = cdiv(Nb, 128);

    for (int L = 0; L < 3; L++) {
        // feature GEMMs (q + folded kt/vt), tensor-core bf16 2-split
        k_gemm_bf16<false, 0><<<dim3(5, mbA), 256, SMEM_GEMM>>>(
            hbuf, 128, Na, wAb + (size_t)L * 8 * 32768, bcat + L * 1024,
            fa, 640, nullptr, nullptr, nullptr);
        k_gemm_bf16<false, 0><<<dim3(3, mbB), 256, SMEM_GEMM>>>(
            hbuf + (size_t)Na * 128, 128, Nb, wAb + ((size_t)L * 8 + 5) * 32768,
            bcat + L * 1024 + 640, fb, 384, nullptr, nullptr, nullptr);
        // fused edge online-softmax aggregate
        k_hgt_edges<<<cdiv(N * 32, 256), 256>>>(fa, fb, rowptrb, cseb,
            prel + L * 12, aggb, Na, N);
        // out GEMM with fused gelu-on-input + skip/LN/gelu epilogue
        for (int t = 0; t < 2; t++) {
            int Nt = t ? Nb : Na;
            size_t off = (size_t)(t ? Na : 0) * 128;
            if (L == 0) {
                k_gemm_bf16<true, 2><<<dim3(1, cdiv(Nt, 128)), 256, SMEM_GEMM>>>(
                    aggb + off, 128, Nt, wOb + (size_t)(L * 2 + t) * 32768,
                    bout + (size_t)(L * 2 + t) * 128, hbuf + off, 128,
                    skip + (L * 2 + t), ln_g + t * 128, ln_b + t * 128);
            } else {
                k_gemm_bf16<true, 1><<<dim3(1, cdiv(Nt, 128)), 256, SMEM_GEMM>>>(
                    aggb + off, 128, Nt, wOb + (size_t)(L * 2 + t) * 32768,
                    bout + (size_t)(L * 2 + t) * 128, hbuf + off, 128,
                    skip + (L * 2 + t), nullptr, nullptr);
            }
        }
    }

    // GAT scorer + SAGPool + MLP
    k_x1<<<cdiv(N * 32, 256), 256>>>(hbuf, Wgat, x1b, N);
    k_gat<<<cdiv(N, 256), 256>>>(x1b, rowptrb, cseb, att_s, att_d, bgat, scoreb, Na, N);
    int nblk = cdiv(N, 256);
    k_topk<<<nblk, 256>>>(scoreb, cvalb, cidxb, N);
    k_final<<<1, 256>>>(hbuf, cvalb, cidxb, nblk * 8,
                        W1, b1, W2, b2, W3, b3, (float*)d_out);
}

// round 7
// speedup vs baseline: 1.8471x; 1.2121x over previous
#include <cuda_runtime.h>
#include <cuda_bf16.h>
#include <math.h>
#include <stdint.h>

#define NAC 20000
#define NBC 20000
#define NNC 40000
#define EC  150000
#define MAXCAND 2048

// ---------------------------------------------------------------------------
// Scratch (static device globals)
// ---------------------------------------------------------------------------
__device__ float g_h[NNC * 128];             // node features [a;b]
__device__ float g_feat_a[NAC * 640];        // q|kt0|vt0|kt1|vt1 for type a
__device__ float g_feat_b[NBC * 384];        // q|kt2|vt2 for type b
__device__ float g_bcat[3 * 1024];           // folded biases
__device__ __align__(16) __nv_bfloat16 g_wA[24 * 32768];  // split/swizzled wcat tiles
__device__ __align__(16) __nv_bfloat16 g_wO[6 * 32768];   // split/swizzled Wout tiles
__device__ float g_agg[NNC * 128];
__device__ int   g_deg[NNC + 1];
__device__ int   g_rowptr[NNC + 1];
__device__ int   g_cursor[NNC];
__device__ int   g_bsum[64];
__device__ int   g_cse[3 * EC];              // src | et<<29
__device__ float g_x1[NNC];
__device__ float g_score[NNC];
__device__ float g_cval[MAXCAND];
__device__ int   g_cidx[MAXCAND];

__device__ __forceinline__ float gelu_f(float x) {
    return 0.5f * x * (1.0f + erff(x * 0.7071067811865475f));
}
__device__ __forceinline__ uint32_t smem_u32(const void* p) {
    uint32_t a;
    asm("{ .reg .u64 t; cvta.to.shared.u64 t, %1; cvt.u32.u64 %0, t; }" : "=r"(a) : "l"(p));
    return a;
}
// mma.sync bf16: D(f32) += A(bf16 m16k16, row) * B(bf16 k16n8, col)
__device__ __forceinline__ void mma_bf16(float* c, const uint32_t* a, const uint32_t* b) {
    asm volatile(
        "mma.sync.aligned.m16n8k16.row.col.f32.bf16.bf16.f32 "
        "{%0,%1,%2,%3}, {%4,%5,%6,%7}, {%8,%9}, {%0,%1,%2,%3};"
        : "+f"(c[0]), "+f"(c[1]), "+f"(c[2]), "+f"(c[3])
        : "r"(a[0]), "r"(a[1]), "r"(a[2]), "r"(a[3]), "r"(b[0]), "r"(b[1]));
}
__device__ __forceinline__ void ldsm_x4(uint32_t* r, uint32_t addr) {
    asm volatile("ldmatrix.sync.aligned.m8n8.x4.shared.b16 {%0,%1,%2,%3}, [%4];"
                 : "=r"(r[0]), "=r"(r[1]), "=r"(r[2]), "=r"(r[3]) : "r"(addr));
}
#define CP_ASYNC16(dst, src) \
    asm volatile("cp.async.cg.shared.global [%0], [%1], 16;" :: "r"(dst), "l"(src))
#define CP_COMMIT() asm volatile("cp.async.commit_group;" ::: "memory")
#define CP_WAIT0()  asm volatile("cp.async.wait_group 0;" ::: "memory")

// split 8 consecutive floats into packed bf16 hi (16B) and lo (16B)
__device__ __forceinline__ void split8(const float* f, uint4& hi, uint4& lo) {
    uint32_t h[4], l[4];
#pragma unroll
    for (int j = 0; j < 4; j++) {
        float f0 = f[2 * j], f1 = f[2 * j + 1];
        __nv_bfloat16 b0 = __float2bfloat16_rn(f0);
        __nv_bfloat16 b1 = __float2bfloat16_rn(f1);
        float r0 = f0 - __bfloat162float(b0);
        float r1 = f1 - __bfloat162float(b1);
        __nv_bfloat162 hh = __halves2bfloat162(b0, b1);
        __nv_bfloat162 ll = __halves2bfloat162(__float2bfloat16_rn(r0),
                                               __float2bfloat16_rn(r1));
        h[j] = *(uint32_t*)&hh;
        l[j] = *(uint32_t*)&ll;
    }
    hi = make_uint4(h[0], h[1], h[2], h[3]);
    lo = make_uint4(l[0], l[1], l[2], l[3]);
}

// ---------------------------------------------------------------------------
// Folded weight value: combined [q | kt/vt per edge-type] weight matrix.
// i in [0,128) = W row (K index); i==128 = bias. c in [0,1024).
// ---------------------------------------------------------------------------
__device__ float fold_val(const float* __restrict__ Wkqv, const float* __restrict__ bkqv,
                          const float* __restrict__ arel, const float* __restrict__ mrel,
                          int L, int i, int c) {
    int type = (c >= 640) ? 1 : 0;
    int cc = c - (type ? 640 : 0);
    int part = cc >> 7, wi = cc & 127;
    const float* Wrow = (i < 128) ? Wkqv + ((size_t)(L * 2 + type) * 128 + i) * 384
                                  : bkqv + (size_t)(L * 2 + type) * 384;
    if (part == 0) return Wrow[128 + wi];
    int et, kv;
    if (type == 0) { et = (part - 1) >> 1; kv = (part - 1) & 1; }
    else           { et = 2;               kv = part - 1; }
    int h = wi >> 5, e2 = wi & 31;
    const float* rel = (kv ? mrel : arel) + ((size_t)(L * 3 + et) * 4 + h) * 1024 + e2;
    const float* ws = Wrow + (kv ? 256 : 0) + h * 32;
    float s = 0.f;
#pragma unroll
    for (int d = 0; d < 32; d++) s += ws[d] * rel[d * 32];
    return s;
}

// ---------------------------------------------------------------------------
// Fold + split + swizzle weights directly into bf16 blobs; also biases.
// Tiles 0..23: wcat (L*8 + colTile). 24..29: Wout. Tail range: bcat.
// ---------------------------------------------------------------------------
__global__ void k_fold2(const float* __restrict__ Wkqv, const float* __restrict__ bkqv,
                        const float* __restrict__ Wout,
                        const float* __restrict__ arel, const float* __restrict__ mrel,
                        __nv_bfloat16* __restrict__ wA, __nv_bfloat16* __restrict__ wO,
                        float* __restrict__ bcat) {
    int idx = blockIdx.x * blockDim.x + threadIdx.x;
    const int PER = 16384;
    const int WTOT = 30 * PER;
    if (idx < WTOT) {
        int t = idx / PER, e = idx % PER;
        int k = e >> 7, n = e & 127;
        float v;
        __nv_bfloat16* dst;
        if (t < 24) {
            int L = t >> 3, xt = t & 7;
            int c = (xt < 5) ? xt * 128 + n : 640 + (xt - 5) * 128 + n;
            v = fold_val(Wkqv, bkqv, arel, mrel, L, k, c);
            dst = wA + (size_t)t * 32768;
        } else {
            v = Wout[(size_t)(t - 24) * 16384 + k * 128 + n];
            dst = wO + (size_t)(t - 24) * 32768;
        }
        __nv_bfloat16 hi = __float2bfloat16_rn(v);
        __nv_bfloat16 lo = __float2bfloat16_rn(v - __bfloat162float(hi));
        int chunk = k >> 6, kk = k & 63;
        int ksw = ((kk * 2) ^ ((n & 7) << 4)) >> 1;
        dst += chunk * 16384;
        dst[n * 64 + ksw] = hi;
        dst[8192 + n * 64 + ksw] = lo;
    } else if (idx < WTOT + 3 * 1024) {
        int j = idx - WTOT;
        int L = j >> 10, c = j & 1023;
        bcat[L * 1024 + c] = fold_val(Wkqv, bkqv, arel, mrel, L, 128, c);
    }
}

// ---------------------------------------------------------------------------
// GEMM core (shared by feature and out kernels): computes a 128x128 tile
// acc = bf16-2split(A[row0..row0+128, 0:128]) @ Wtile, A fp32 (optional gelu).
// 256 threads = 8 warps (2 M x 4 N).
// ---------------------------------------------------------------------------
#define SMEM_GEMM 65536
template <bool GELU_A>
__device__ __forceinline__ void gemm_tile(char* smem, uint32_t sb,
                                          const float* __restrict__ A, int lda, int arows,
                                          const __nv_bfloat16* __restrict__ blob,
                                          float acc[4][4][4]) {
    const int AHI = 0, ALO = 16384, BHI = 32768;
    int tid = threadIdx.x, lane = tid & 31, wid = tid >> 5;
    int warp_m = wid & 1, warp_n = wid >> 1;
    int lm = lane & 15;
    int lk = (lane >> 4) << 4;

    for (int chunk = 0; chunk < 2; chunk++) {
        // ---- B: cp.async linear copy of pre-swizzled blob chunk (32KB)
        {
            const char* src = (const char*)(blob + chunk * 16384);
            uint32_t dst = sb + BHI;
#pragma unroll
            for (int it = 0; it < 8; it++) {
                int i = it * 256 + tid;
                CP_ASYNC16(dst + i * 16, src + i * 16);
            }
            CP_COMMIT();
        }
        // ---- A: load 128x64 fp32, optional gelu, bf16 hi/lo split, swizzled STS
#pragma unroll
        for (int it = 0; it < 4; it++) {
            int i = it * 256 + tid;
            int m = i >> 3, kg = i & 7;
            float f[8] = {};
            if (m < arows) {
                const float* ap = A + (size_t)m * lda + chunk * 64 + kg * 8;
                *(float4*)&f[0] = *(const float4*)ap;
                *(float4*)&f[4] = *(const float4*)(ap + 4);
            }
            if (GELU_A) {
#pragma unroll
                for (int j = 0; j < 8; j++) f[j] = gelu_f(f[j]);
            }
            uint4 hi, lo;
            split8(f, hi, lo);
            int off = m * 128 + ((kg * 16) ^ ((m & 7) << 4));
            *(uint4*)(smem + AHI + off) = hi;
            *(uint4*)(smem + ALO + off) = lo;
        }
        CP_WAIT0();
        __syncthreads();

#pragma unroll
        for (int k16 = 0; k16 < 4; k16++) {
            int kb = k16 * 32 + lk;
            uint32_t bh[2][4], bl[2][4];
#pragma unroll
            for (int ntp = 0; ntp < 2; ntp++) {
                int n = warp_n * 32 + ntp * 16 + lm;
                int off = n * 128 + (kb ^ ((n & 7) << 4));
                ldsm_x4(bh[ntp], sb + BHI + off);
                ldsm_x4(bl[ntp], sb + BHI + 16384 + off);
            }
#pragma unroll
            for (int mt = 0; mt < 4; mt++) {
                int m = warp_m * 64 + mt * 16 + lm;
                int off = m * 128 + (kb ^ ((m & 7) << 4));
                uint32_t ah[4], al[4];
                ldsm_x4(ah, sb + AHI + off);
                ldsm_x4(al, sb + ALO + off);
#pragma unroll
                for (int nt = 0; nt < 4; nt++) {
                    uint32_t bfh[2] = {bh[nt >> 1][nt & 1], bh[nt >> 1][(nt & 1) + 2]};
                    uint32_t bfl[2] = {bl[nt >> 1][nt & 1], bl[nt >> 1][(nt & 1) + 2]};
                    mma_bf16(acc[mt][nt], ah, bfh);
                    mma_bf16(acc[mt][nt], ah, bfl);
                    mma_bf16(acc[mt][nt], al, bfh);
                }
            }
        }
        __syncthreads();
    }
}

// ---------------------------------------------------------------------------
// Merged feature GEMM: one launch per layer, both node types.
// grid = (8, maxMtiles). x<5: type a -> Ca (ld 640); x>=5: type b -> Cb (ld 384).
// ---------------------------------------------------------------------------
__global__ void __launch_bounds__(256)
k_gemm_feat(const float* __restrict__ Aa, const float* __restrict__ Ab,
            int Ma, int Mb,
            const __nv_bfloat16* __restrict__ wblob, const float* __restrict__ bias,
            float* __restrict__ Ca, float* __restrict__ Cb) {
    extern __shared__ __align__(128) char smem[];
    uint32_t sb = smem_u32(smem);
    int xt = blockIdx.x;
    bool tb = xt >= 5;
    const float* A = tb ? Ab : Aa;
    int M = tb ? Mb : Ma;
    float* C = tb ? Cb : Ca;
    int ldc = tb ? 384 : 640;
    int coloff = tb ? (xt - 5) * 128 : xt * 128;
    int biasoff = tb ? 640 + (xt - 5) * 128 : xt * 128;
    int row0 = blockIdx.y << 7;
    if (row0 >= M) return;

    float acc[4][4][4] = {};
    gemm_tile<false>(smem, sb, A + (size_t)row0 * 128, 128, M - row0,
                     wblob + (size_t)xt * 32768, acc);

    int lane = threadIdx.x & 31, wid = threadIdx.x >> 5;
    int warp_m = wid & 1, warp_n = wid >> 1;
    int crow = lane >> 2, ccol = (lane & 3) * 2;
#pragma unroll
    for (int nt = 0; nt < 4; nt++) {
        int nl = warp_n * 32 + nt * 8 + ccol;
        float b0 = bias[biasoff + nl], b1 = bias[biasoff + nl + 1];
#pragma unroll
        for (int mt = 0; mt < 4; mt++) {
            int m = row0 + warp_m * 64 + mt * 16 + crow;
            if (m < M) {
                float2 o = make_float2(acc[mt][nt][0] + b0, acc[mt][nt][1] + b1);
                *(float2*)(C + (size_t)m * ldc + coloff + nl) = o;
            }
            if (m + 8 < M) {
                float2 o = make_float2(acc[mt][nt][2] + b0, acc[mt][nt][3] + b1);
                *(float2*)(C + (size_t)(m + 8) * ldc + coloff + nl) = o;
            }
        }
    }
}

// ---------------------------------------------------------------------------
// Merged out GEMM + epilogue: one launch per layer, both node types.
// grid = (1, mtA + mtB).  A = gelu(agg).  ssrc = skip source (x at L0, h else).
// EPI=1: h = gelu( s*(A@W+b) + (1-s)*ssrc ).  EPI=2: with LN before gelu.
// ---------------------------------------------------------------------------
template <int EPI>
__global__ void __launch_bounds__(256)
k_gemm_out(const float* __restrict__ agg, int Ma, int Mb, int mtA,
           const __nv_bfloat16* __restrict__ wblob, const float* __restrict__ bias2,
           float* __restrict__ hbuf,
           const float* __restrict__ ssa, const float* __restrict__ ssb,
           const float* __restrict__ skip2,
           const float* __restrict__ lng, const float* __restrict__ lnb) {
    extern __shared__ __align__(128) char smem[];
    uint32_t sb = smem_u32(smem);
    int yt = blockIdx.y;
    bool tb = yt >= mtA;
    int row0 = (tb ? yt - mtA : yt) << 7;
    int M = tb ? Mb : Ma;
    if (row0 >= M) return;
    const float* A = agg + (tb ? (size_t)Ma * 128 : 0);
    const __nv_bfloat16* blob = wblob + (tb ? 32768 : 0);
    const float* bias = bias2 + (tb ? 128 : 0);
    float* C = hbuf + (tb ? (size_t)Ma * 128 : 0);
    const float* ssrc = tb ? ssb : ssa;
    const float* lg = lng + (tb ? 128 : 0);
    const float* lb = lnb + (tb ? 128 : 0);

    float acc[4][4][4] = {};
    gemm_tile<true>(smem, sb, A + (size_t)row0 * 128, 128, M - row0, blob, acc);

    int tid = threadIdx.x, lane = tid & 31, wid = tid >> 5;
    int warp_m = wid & 1, warp_n = wid >> 1;
    int crow = lane >> 2, ccol = (lane & 3) * 2;

    float sg = 1.f / (1.f + expf(-skip2[tb ? 1 : 0]));
#pragma unroll
    for (int nt = 0; nt < 4; nt++) {
        int nl = warp_n * 32 + nt * 8 + ccol;
        float b0 = bias[nl], b1 = bias[nl + 1];
#pragma unroll
        for (int mt = 0; mt < 4; mt++) {
            int m = row0 + warp_m * 64 + mt * 16 + crow;
            if (m < M) {
                float2 h0 = *(const float2*)(ssrc + (size_t)m * 128 + nl);
                acc[mt][nt][0] = sg * (acc[mt][nt][0] + b0) + (1.f - sg) * h0.x;
                acc[mt][nt][1] = sg * (acc[mt][nt][1] + b1) + (1.f - sg) * h0.y;
            }
            if (m + 8 < M) {
                float2 h1 = *(const float2*)(ssrc + (size_t)(m + 8) * 128 + nl);
                acc[mt][nt][2] = sg * (acc[mt][nt][2] + b0) + (1.f - sg) * h1.x;
                acc[mt][nt][3] = sg * (acc[mt][nt][3] + b1) + (1.f - sg) * h1.y;
            }
        }
    }
    if (EPI == 2) {
        float* ssum = (float*)smem;
        float* ssq  = ssum + 128;
        if (tid < 128) { ssum[tid] = 0.f; ssq[tid] = 0.f; }
        __syncthreads();
#pragma unroll
        for (int mt = 0; mt < 4; mt++) {
#pragma unroll
            for (int half = 0; half < 2; half++) {
                float p = 0.f, q = 0.f;
#pragma unroll
                for (int nt = 0; nt < 4; nt++) {
                    float v0 = acc[mt][nt][half * 2];
                    float v1 = acc[mt][nt][half * 2 + 1];
                    p += v0 + v1; q += v0 * v0 + v1 * v1;
                }
                p += __shfl_xor_sync(~0u, p, 1); q += __shfl_xor_sync(~0u, q, 1);
                p += __shfl_xor_sync(~0u, p, 2); q += __shfl_xor_sync(~0u, q, 2);
                if ((lane & 3) == 0) {
                    int row = warp_m * 64 + mt * 16 + half * 8 + crow;
                    atomicAdd(&ssum[row], p);
                    atomicAdd(&ssq[row], q);
                }
            }
        }
        __syncthreads();
#pragma unroll
        for (int mt = 0; mt < 4; mt++) {
            int r0 = warp_m * 64 + mt * 16 + crow;
            float mu0 = ssum[r0] * 0.0078125f;
            float rs0 = rsqrtf(ssq[r0] * 0.0078125f - mu0 * mu0 + 1e-5f);
            float mu1 = ssum[r0 + 8] * 0.0078125f;
            float rs1 = rsqrtf(ssq[r0 + 8] * 0.0078125f - mu1 * mu1 + 1e-5f);
            int m = row0 + r0;
#pragma unroll
            for (int nt = 0; nt < 4; nt++) {
                int nl = warp_n * 32 + nt * 8 + ccol;
                float g0 = lg[nl], g1 = lg[nl + 1];
                float e0 = lb[nl], e1 = lb[nl + 1];
                if (m < M) {
                    float2 o;
                    o.x = gelu_f((acc[mt][nt][0] - mu0) * rs0 * g0 + e0);
                    o.y = gelu_f((acc[mt][nt][1] - mu0) * rs0 * g1 + e1);
                    *(float2*)(C + (size_t)m * 128 + nl) = o;
                }
                if (m + 8 < M) {
                    float2 o;
                    o.x = gelu_f((acc[mt][nt][2] - mu1) * rs1 * g0 + e0);
                    o.y = gelu_f((acc[mt][nt][3] - mu1) * rs1 * g1 + e1);
                    *(float2*)(C + (size_t)(m + 8) * 128 + nl) = o;
                }
            }
        }
    } else {
#pragma unroll
        for (int nt = 0; nt < 4; nt++) {
            int nl = warp_n * 32 + nt * 8 + ccol;
#pragma unroll
            for (int mt = 0; mt < 4; mt++) {
                int m = row0 + warp_m * 64 + mt * 16 + crow;
                if (m < M) {
                    float2 o = make_float2(gelu_f(acc[mt][nt][0]), gelu_f(acc[mt][nt][1]));
                    *(float2*)(C + (size_t)m * 128 + nl) = o;
                }
                if (m + 8 < M) {
                    float2 o = make_float2(gelu_f(acc[mt][nt][2]), gelu_f(acc[mt][nt][3]));
                    *(float2*)(C + (size_t)(m + 8) * 128 + nl) = o;
                }
            }
        }
    }
}

// ---------------------------------------------------------------------------
// CSR build
// ---------------------------------------------------------------------------
__global__ void k_zero_deg(int* d, int n) {
    int i = blockIdx.x * blockDim.x + threadIdx.x;
    if (i < n) d[i] = 0;
}
__global__ void k_count(const int* __restrict__ aa, const int* __restrict__ ab,
                        const int* __restrict__ ba, int* __restrict__ deg, int E, int Na) {
    int i = blockIdx.x * blockDim.x + threadIdx.x;
    if (i >= 3 * E) return;
    int dst;
    if (i < E) dst = aa[E + i];
    else if (i < 2 * E) dst = ab[E + (i - E)] + Na;
    else dst = ba[E + (i - 2 * E)];
    atomicAdd(&deg[dst + 1], 1);
}
__global__ void k_scan1(const int* __restrict__ deg, int* __restrict__ rowptr,
                        int* __restrict__ bsum, int n) {
    __shared__ int buf[1024];
    int i = blockIdx.x * 1024 + threadIdx.x;
    int v = (i < n) ? deg[i] : 0;
    buf[threadIdx.x] = v;
    __syncthreads();
    for (int o = 1; o < 1024; o <<= 1) {
        int u = (threadIdx.x >= o) ? buf[threadIdx.x - o] : 0;
        __syncthreads();
        buf[threadIdx.x] += u;
        __syncthreads();
    }
    if (i < n) rowptr[i] = buf[threadIdx.x];
    if (threadIdx.x == 1023) bsum[blockIdx.x] = buf[1023];
}
__global__ void k_scan2(int* __restrict__ bsum, int nb) {
    __shared__ int s[64];
    int t = threadIdx.x;
    int v = (t < nb) ? bsum[t] : 0;
    s[t] = v;
    __syncthreads();
    for (int o = 1; o < 64; o <<= 1) {
        int u = (t >= o) ? s[t - o] : 0;
        __syncthreads();
        s[t] += u;
        __syncthreads();
    }
    if (t < nb) bsum[t] = s[t] - v;   // exclusive
}
__global__ void k_scan3(const int* __restrict__ bsum, int* __restrict__ rowptr,
                        int* __restrict__ cursor, int n, int N) {
    int i = blockIdx.x * blockDim.x + threadIdx.x;
    if (i >= n) return;
    int v = rowptr[i] + bsum[i >> 10];
    rowptr[i] = v;
    if (i < N) cursor[i] = v;
}
__global__ void k_fill(const int* __restrict__ aa, const int* __restrict__ ab,
                       const int* __restrict__ ba, int* __restrict__ cursor,
                       int* __restrict__ cse, int E, int Na) {
    int i = blockIdx.x * blockDim.x + threadIdx.x;
    if (i >= 3 * E) return;
    int src, dst, et;
    if (i < E)            { et = 0; src = aa[i]; dst = aa[E + i]; }
    else if (i < 2 * E)   { et = 1; int j = i - E;     src = ab[j]; dst = ab[E + j] + Na; }
    else                  { et = 2; int j = i - 2 * E; src = ba[j]; dst = ba[E + j]; }
    int pos = atomicAdd(&cursor[dst], 1);
    cse[pos] = src | (et << 29);
}

// ---------------------------------------------------------------------------
// Fused HGT edge online-softmax aggregate. One warp per dst node. Single pass.
// ---------------------------------------------------------------------------
__global__ void k_hgt_edges(const float* __restrict__ fa, const float* __restrict__ fb,
                            const int* __restrict__ rowptr, const int* __restrict__ cse,
                            const float* __restrict__ prelL,
                            float* __restrict__ agg, int Na, int N) {
    __shared__ float sp[12];
    if (threadIdx.x < 12) sp[threadIdx.x] = prelL[threadIdx.x];
    __syncthreads();
    int warp = (blockIdx.x * blockDim.x + threadIdx.x) >> 5;
    int lane = threadIdx.x & 31;
    if (warp >= N) return;
    int n = warp;
    const float* qrow = (n < Na) ? (fa + (size_t)n * 640) : (fb + (size_t)(n - Na) * 384);
    float4 q4 = *(const float4*)(qrow + lane * 4);
    int h = lane >> 3;
    int beg = rowptr[n], end = rowptr[n + 1];

    float mx = -INFINITY, sum = 0.f;
    float4 acc = make_float4(0.f, 0.f, 0.f, 0.f);

    int idx = beg;
    int p = 0;
    float4 k4 = {}, v4 = {};
    if (idx < end) {
        p = cse[idx];
        int et = p >> 29, src = p & 0x1FFFFFFF;
        const float* base = (et < 2) ? (fa + (size_t)src * 640 + 128 + (et << 8))
                                     : (fb + (size_t)src * 384 + 128);
        k4 = *(const float4*)(base + lane * 4);
        v4 = *(const float4*)(base + 128 + lane * 4);
    }
    while (idx < end) {
        int pn = 0;
        float4 k4n = {}, v4n = {};
        if (idx + 1 < end) {
            pn = cse[idx + 1];
            int etn = pn >> 29, srcn = pn & 0x1FFFFFFF;
            const float* basen = (etn < 2) ? (fa + (size_t)srcn * 640 + 128 + (etn << 8))
                                           : (fb + (size_t)srcn * 384 + 128);
            k4n = *(const float4*)(basen + lane * 4);
            v4n = *(const float4*)(basen + 128 + lane * 4);
        }
        int et = p >> 29;
        float s = q4.x * k4.x + q4.y * k4.y + q4.z * k4.z + q4.w * k4.w;
        s += __shfl_xor_sync(0xffffffffu, s, 1);
        s += __shfl_xor_sync(0xffffffffu, s, 2);
        s += __shfl_xor_sync(0xffffffffu, s, 4);
        float lg = s * sp[et * 4 + h] * 0.17677669529663687f;  // /sqrt(32)
        float mnew = fmaxf(mx, lg);
        float corr = expf(mx - mnew);
        float w = expf(lg - mnew);
        sum = sum * corr + w;
        acc.x = acc.x * corr + w * v4.x;
        acc.y = acc.y * corr + w * v4.y;
        acc.z = acc.z * corr + w * v4.z;
        acc.w = acc.w * corr + w * v4.w;
        mx = mnew;
        p = pn; k4 = k4n; v4 = v4n; idx++;
    }
    float inv = 1.f / (sum + 1e-16f);
    acc.x *= inv; acc.y *= inv; acc.z *= inv; acc.w *= inv;
    *(float4*)(agg + (size_t)n * 128 + lane * 4) = acc;
}

// ---------------------------------------------------------------------------
// GAT scorer via CSR (+analytic self loops), online softmax, one pass
// ---------------------------------------------------------------------------
__global__ void k_x1(const float* __restrict__ h, const float* __restrict__ Wg,
                     float* __restrict__ x1, int N) {
    int gw = (blockIdx.x * blockDim.x + threadIdx.x) >> 5;
    int lane = threadIdx.x & 31;
    if (gw >= N) return;
    const float* row = h + (size_t)gw * 128;
    float v = row[lane] * Wg[lane] + row[32 + lane] * Wg[32 + lane]
            + row[64 + lane] * Wg[64 + lane] + row[96 + lane] * Wg[96 + lane];
    v += __shfl_down_sync(0xffffffffu, v, 16);
    v += __shfl_down_sync(0xffffffffu, v, 8);
    v += __shfl_down_sync(0xffffffffu, v, 4);
    v += __shfl_down_sync(0xffffffffu, v, 2);
    v += __shfl_down_sync(0xffffffffu, v, 1);
    if (lane == 0) x1[gw] = v;
}

__global__ void k_gat(const float* __restrict__ x1, const int* __restrict__ rowptr,
                      const int* __restrict__ cse, const float* __restrict__ as_,
                      const float* __restrict__ ad_, const float* __restrict__ bg,
                      float* __restrict__ score, int Na, int N) {
    int n = blockIdx.x * blockDim.x + threadIdx.x;
    if (n >= N) return;
    float a_s = as_[0], a_d = ad_[0];
    float xd = x1[n];
    float eself = xd * (a_s + a_d);
    eself = eself > 0.f ? eself : 0.2f * eself;
    float m = eself, sum = 1.f, num = xd;    // self loop: w=exp(0)=1
    int beg = rowptr[n], end = rowptr[n + 1];
    for (int i = beg; i < end; i++) {
        int p = cse[i];
        int src = (p & 0x1FFFFFFF) + (((p >> 29) == 2) ? Na : 0);
        float xs = x1[src];
        float e = xs * a_s + xd * a_d;
        e = e > 0.f ? e : 0.2f * e;
        float mnew = fmaxf(m, e);
        float corr = expf(m - mnew);
        float w = expf(e - mnew);
        sum = sum * corr + w;
        num = num * corr + w * xs;
        m = mnew;
    }
    score[n] = num / (sum + 1e-16f) + bg[0];
}

// ---------------------------------------------------------------------------
// Top-K prepass: each block emits its local top-8 (val desc, idx asc)
// ---------------------------------------------------------------------------
__global__ void k_topk(const float* __restrict__ score, float* __restrict__ cval,
                       int* __restrict__ cidx, int N) {
    const float NEG_INF = __int_as_float(0xff800000);
    __shared__ float sval[256];
    __shared__ int   sida[256];
    __shared__ float sred[256];
    __shared__ int   sidr[256];
    int t = threadIdx.x;
    int i = blockIdx.x * 256 + t;
    sval[t] = (i < N) ? score[i] : NEG_INF;
    sida[t] = (i < N) ? i : 0x7fffffff;
    __syncthreads();
    for (int k = 0; k < 8; k++) {
        sred[t] = sval[t]; sidr[t] = sida[t];
        __syncthreads();
        for (int s = 128; s > 0; s >>= 1) {
            if (t < s) {
                if (sred[t + s] > sred[t] ||
                    (sred[t + s] == sred[t] && sidr[t + s] < sidr[t])) {
                    sred[t] = sred[t + s]; sidr[t] = sidr[t + s];
                }
            }
            __syncthreads();
        }
        int win = sidr[0];
        if (t == 0) {
            cval[blockIdx.x * 8 + k] = sred[0];
            cidx[blockIdx.x * 8 + k] = win;
        }
        if (sida[t] == win) sval[t] = NEG_INF;
        __syncthreads();
    }
}

// ---------------------------------------------------------------------------
// Final: global top-8 from candidates, gated readout, 3-layer MLP, nan_to_num.
// ---------------------------------------------------------------------------
__global__ void k_final(const float* __restrict__ h,
                        const float* __restrict__ cval, const int* __restrict__ cidx,
                        int ncand,
                        const float* __restrict__ W1, const float* __restrict__ b1,
                        const float* __restrict__ W2, const float* __restrict__ b2,
                        const float* __restrict__ W3, const float* __restrict__ b3,
                        float* __restrict__ out) {
    const float NEG_INF = __int_as_float(0xff800000);
    __shared__ float cv[MAXCAND];
    __shared__ int   ci[MAXCAND];
    __shared__ float sred[256];
    __shared__ int   sidx[256];
    __shared__ float hp[1024];
    __shared__ int   perm[8];
    __shared__ float vals[8];
    __shared__ float v1[128];
    __shared__ float v2[64];
    int t = threadIdx.x;

    for (int i = t; i < MAXCAND; i += 256) {
        cv[i] = (i < ncand) ? cval[i] : NEG_INF;
        ci[i] = (i < ncand) ? cidx[i] : 0x7fffffff;
    }
    __syncthreads();

    for (int k = 0; k < 8; k++) {
        float bv = NEG_INF; int bi = 0x7fffffff;
        for (int i = t; i < MAXCAND; i += 256) {
            float v = cv[i];
            if (v > bv || (v == bv && ci[i] < bi)) { bv = v; bi = ci[i]; }
        }
        sred[t] = bv; sidx[t] = bi;
        __syncthreads();
        for (int s = 128; s > 0; s >>= 1) {
            if (t < s) {
                if (sred[t + s] > sred[t] ||
                    (sred[t + s] == sred[t] && sidx[t + s] < sidx[t])) {
                    sred[t] = sred[t + s]; sidx[t] = sidx[t + s];
                }
            }
            __syncthreads();
        }
        int win = sidx[0];
        if (t == 0) { perm[k] = win; vals[k] = sred[0]; }
        for (int i = t; i < MAXCAND; i += 256)
            if (ci[i] == win) cv[i] = NEG_INF;
        __syncthreads();
    }

    for (int i = t; i < 1024; i += 256) {
        int k = i >> 7, j = i & 127;
        hp[i] = h[(size_t)perm[k] * 128 + j] * tanhf(vals[k]);
    }
    __syncthreads();

    if (t < 128) {
        float acc = b1[t];
        for (int i = 0; i < 1024; i++) acc += hp[i] * W1[i * 128 + t];
        v1[t] = gelu_f(acc);
    }
    __syncthreads();
    if (t < 64) {
        float acc = b2[t];
        for (int i = 0; i < 128; i++) acc += v1[i] * W2[i * 64 + t];
        v2[t] = gelu_f(acc);
    }
    __syncthreads();
    if (t < 16) {
        float acc = b3[t];
        for (int i = 0; i < 64; i++) acc += v2[i] * W3[i * 16 + t];
        float r = gelu_f(acc);
        if (isnan(r)) r = 0.f;
        else if (isinf(r)) r = (r > 0.f) ? 3.4028234663852886e38f : -3.4028234663852886e38f;
        out[t] = r;
    }
}

// ---------------------------------------------------------------------------
static inline int cdiv(int a, int b) { return (a + b - 1) / b; }

extern "C" void kernel_launch(void* const* d_in, const int* in_sizes, int n_in,
                              void* d_out, int out_size) {
    const float* x_a   = (const float*)d_in[0];
    const float* x_b   = (const float*)d_in[1];
    const int*   ei_aa = (const int*)d_in[2];
    const int*   ei_ab = (const int*)d_in[3];
    const int*   ei_ba = (const int*)d_in[4];
    const float* Wkqv  = (const float*)d_in[5];
    const float* bkqv  = (const float*)d_in[6];
    const float* Wout  = (const float*)d_in[7];
    const float* bout  = (const float*)d_in[8];
    const float* skip  = (const float*)d_in[9];
    const float* arel  = (const float*)d_in[10];
    const float* mrel  = (const float*)d_in[11];
    const float* prel  = (const float*)d_in[12];
    const float* ln_g  = (const float*)d_in[13];
    const float* ln_b  = (const float*)d_in[14];
    const float* Wgat  = (const float*)d_in[15];
    const float* att_s = (const float*)d_in[16];
    const float* att_d = (const float*)d_in[17];
    const float* bgat  = (const float*)d_in[18];
    const float* W1    = (const float*)d_in[19];
    const float* b1    = (const float*)d_in[20];
    const float* W2    = (const float*)d_in[21];
    const float* b2    = (const float*)d_in[22];
    const float* W3    = (const float*)d_in[23];
    const float* b3    = (const float*)d_in[24];

    int Na = in_sizes[0] / 128;
    int Nb = in_sizes[1] / 128;
    int N  = Na + Nb;
    int E  = in_sizes[2] / 2;

    float *hbuf, *fa, *fb, *bcat, *aggb, *x1b, *scoreb, *cvalb;
    __nv_bfloat16 *wAb, *wOb;
    int *degb, *rowptrb, *cursorb, *cseb, *bsumb, *cidxb;
    cudaGetSymbolAddress((void**)&hbuf, g_h);
    cudaGetSymbolAddress((void**)&fa, g_feat_a);
    cudaGetSymbolAddress((void**)&fb, g_feat_b);
    cudaGetSymbolAddress((void**)&bcat, g_bcat);
    cudaGetSymbolAddress((void**)&wAb, g_wA);
    cudaGetSymbolAddress((void**)&wOb, g_wO);
    cudaGetSymbolAddress((void**)&aggb, g_agg);
    cudaGetSymbolAddress((void**)&degb, g_deg);
    cudaGetSymbolAddress((void**)&rowptrb, g_rowptr);
    cudaGetSymbolAddress((void**)&cursorb, g_cursor);
    cudaGetSymbolAddress((void**)&cseb, g_cse);
    cudaGetSymbolAddress((void**)&bsumb, g_bsum);
    cudaGetSymbolAddress((void**)&x1b, g_x1);
    cudaGetSymbolAddress((void**)&scoreb, g_score);
    cudaGetSymbolAddress((void**)&cvalb, g_cval);
    cudaGetSymbolAddress((void**)&cidxb, g_cidx);

    cudaFuncSetAttribute(k_gemm_feat,   cudaFuncAttributeMaxDynamicSharedMemorySize, SMEM_GEMM);
    cudaFuncSetAttribute(k_gemm_out<1>, cudaFuncAttributeMaxDynamicSharedMemorySize, SMEM_GEMM);
    cudaFuncSetAttribute(k_gemm_out<2>, cudaFuncAttributeMaxDynamicSharedMemorySize, SMEM_GEMM);

    // CSR build + weight fold/prep (reused across layers)
    int n1 = N + 1;
    int nbk = cdiv(n1, 1024);
    k_zero_deg<<<cdiv(n1, 256), 256>>>(degb, n1);
    k_count<<<cdiv(3 * E, 256), 256>>>(ei_aa, ei_ab, ei_ba, degb, E, Na);
    k_scan1<<<nbk, 1024>>>(degb, rowptrb, bsumb, n1);
    k_scan2<<<1, 64>>>(bsumb, nbk);
    k_scan3<<<cdiv(n1, 256), 256>>>(bsumb, rowptrb, cursorb, n1, N);
    k_fill<<<cdiv(3 * E, 256), 256>>>(ei_aa, ei_ab, ei_ba, cursorb, cseb, E, Na);
    k_fold2<<<cdiv(30 * 16384 + 3 * 1024, 256), 256>>>(Wkqv, bkqv, Wout, arel, mrel,
                                                       wAb, wOb, bcat);

    int mbA = cdiv(Na, 128), mbB = cdiv(Nb, 128);
    int mbMax = mbA > mbB ? mbA : mbB;

    for (int L = 0; L < 3; L++) {
        const float* Aa = (L == 0) ? x_a : hbuf;
        const float* Ab = (L == 0) ? x_b : hbuf + (size_t)Na * 128;
        // merged feature GEMM (both types, q + folded kt/vt)
        k_gemm_feat<<<dim3(8, mbMax), 256, SMEM_GEMM>>>(
            Aa, Ab, Na, Nb, wAb + (size_t)L * 8 * 32768, bcat + L * 1024, fa, fb);
        // fused edge online-softmax aggregate
        k_hgt_edges<<<cdiv(N * 32, 256), 256>>>(fa, fb, rowptrb, cseb,
            prel + L * 12, aggb, Na, N);
        // merged out GEMM + fused skip/[LN]/gelu epilogue
        if (L == 0) {
            k_gemm_out<2><<<dim3(1, mbA + mbB), 256, SMEM_GEMM>>>(
                aggb, Na, Nb, mbA, wOb + (size_t)L * 2 * 32768, bout + L * 2 * 128,
                hbuf, x_a, x_b, skip + L * 2, ln_g, ln_b);
        } else {
            k_gemm_out<1><<<dim3(1, mbA + mbB), 256, SMEM_GEMM>>>(
                aggb, Na, Nb, mbA, wOb + (size_t)L * 2 * 32768, bout + L * 2 * 128,
                hbuf, hbuf, hbuf + (size_t)Na * 128, skip + L * 2, ln_g, ln_b);
        }
    }

    // GAT scorer + SAGPool + MLP
    k_x1<<<cdiv(N * 32, 256), 256>>>(hbuf, Wgat, x1b, N);
    k_gat<<<cdiv(N, 256), 256>>>(x1b, rowptrb, cseb, att_s, att_d, bgat, scoreb, Na, N);
    int nblk = cdiv(N, 256);
    k_topk<<<nblk, 256>>>(scoreb, cvalb, cidxb, N);
    k_final<<<1, 256>>>(hbuf, cvalb, cidxb, nblk * 8,
                        W1, b1, W2, b2, W3, b3, (float*)d_out);
}